// round 8
// baseline (speedup 1.0000x reference)
#include <cuda_runtime.h>
#include <cuda_fp16.h>
#include <math.h>
#include <stdint.h>

#define BATCH 4
#define NQ    2048
#define NCTX  1024
#define DIMM  1024
#define HEADS 16
#define DHEAD 64
#define FFI   4096

// ------------------------- static scratch ---------------------------------
__device__ __align__(1024) __half g_xnh [(size_t)BATCH*NQ*DIMM];
__device__ __align__(1024) __half g_xnl [(size_t)BATCH*NQ*DIMM];
__device__ __align__(1024) __half g_cnh [(size_t)BATCH*NCTX*DIMM];
__device__ __align__(1024) __half g_cnl [(size_t)BATCH*NCTX*DIMM];
__device__ __align__(1024) __half g_Qh  [(size_t)BATCH*HEADS*NQ*DHEAD];
__device__ __align__(1024) __half g_Kh  [(size_t)BATCH*NCTX*DHEAD];
__device__ __align__(1024) __half g_Kl  [(size_t)BATCH*NCTX*DHEAD];
__device__ __align__(1024) __half g_Vth [(size_t)BATCH*DHEAD*NCTX];
__device__ __align__(1024) __half g_atth[(size_t)BATCH*NQ*DIMM];
__device__ __align__(1024) __half g_ah  [(size_t)BATCH*NQ*FFI];
__device__ __align__(1024) __half g_Wqh [(size_t)DIMM*DIMM];
__device__ __align__(1024) __half g_Wql [(size_t)DIMM*DIMM];
__device__ __align__(1024) __half g_Wkh [(size_t)2*DHEAD*DIMM];
__device__ __align__(1024) __half g_Wkl [(size_t)2*DHEAD*DIMM];
__device__ __align__(1024) __half g_Woh [(size_t)DIMM*DIMM];
__device__ __align__(1024) __half g_Wol [(size_t)DIMM*DIMM];
__device__ __align__(1024) __half g_W1h [(size_t)2*FFI*DIMM];
__device__ __align__(1024) __half g_W1l [(size_t)2*FFI*DIMM];
__device__ __align__(1024) __half g_W2h [(size_t)DIMM*FFI];
__device__ __align__(1024) __half g_W2l [(size_t)DIMM*FFI];

// ------------------------- helpers ----------------------------------------
__device__ __forceinline__ uint32_t smem_u32(const void* p) {
    uint32_t a;
    asm("{ .reg .u64 t; cvta.to.shared.u64 t, %1; cvt.u32.u64 %0, t; }" : "=r"(a) : "l"(p));
    return a;
}
#define SWZ(x) ((x) ^ (((x) >> 3) & 0x70))
__device__ __forceinline__ void cp16(uint32_t dst, const void* src) {
    asm volatile("cp.async.cg.shared.global [%0], [%1], 16;\n" :: "r"(dst), "l"(src));
}
#define CP_COMMIT() asm volatile("cp.async.commit_group;\n" ::: "memory")
#define CP_WAIT0()  asm volatile("cp.async.wait_group 0;\n"  ::: "memory")
__device__ __forceinline__ void ldsm4(uint32_t* r, uint32_t a) {
    asm volatile("ldmatrix.sync.aligned.m8n8.x4.shared.b16 {%0,%1,%2,%3}, [%4];"
                 : "=r"(r[0]), "=r"(r[1]), "=r"(r[2]), "=r"(r[3]) : "r"(a));
}
__device__ __forceinline__ void mma(float* c, const uint32_t* a, const uint32_t* b) {
    asm volatile("mma.sync.aligned.m16n8k16.row.col.f32.f16.f16.f32 "
                 "{%0,%1,%2,%3}, {%4,%5,%6,%7}, {%8,%9}, {%0,%1,%2,%3};"
                 : "+f"(c[0]), "+f"(c[1]), "+f"(c[2]), "+f"(c[3])
                 : "r"(a[0]), "r"(a[1]), "r"(a[2]), "r"(a[3]), "r"(b[0]), "r"(b[1]));
}

// ------------------------- GEMM (HMMA split-fp16) -------------------------
// C[M x Ntot] = A[M,K] @ B[N,K]^T ; BM=128, BN=TN, BK=64, 8 warps.
// TERMS=3 (TN=64 only): AhBh+AhBl+AlBh, 4 stages.
// TERMS=2: AhBh+AhBl.  TN=64: 3x32KB (2 CTA/SM).  TN=128: 3x48KB (1 CTA/SM).
// MODE: 0 f32 store, 1 f32 add, 3 Q-hi(scale), 4 KV-split, 6 ff-silu
template <int MODE, int TERMS, int TN>
__global__ void __launch_bounds__(256, (TERMS == 2 && TN == 64) ? 2 : 1) gemm_hs(
    const __half* __restrict__ Ah, const __half* __restrict__ Al,
    const __half* __restrict__ Bh, const __half* __restrict__ Bl,
    float* __restrict__ Cf, int K, int ldn, int rpbA, size_t bstrB)
{
    constexpr int TA     = (TERMS == 3) ? 2 : 1;
    constexpr int OFF_AL = 16384;
    constexpr int OFF_BH = 16384 * TA;
    constexpr int BB     = TN * 128;
    constexpr int OFF_BL = OFF_BH + BB;
    constexpr int STAGE  = OFF_BH + 2 * BB;
    constexpr int NS     = (TERMS == 3) ? 4 : 3;
    constexpr int NP     = NS - 1;
    constexpr int JN     = TN / 16;        // n8-tile pairs per warp: 4 or 8
    constexpr int BF     = JN / 2;         // ldsm4 groups for B: 2 or 4
    extern __shared__ char smem[];
    uint32_t t0 = smem_u32(smem);
    int tid = threadIdx.x, lane = tid & 31, wid = tid >> 5;

    // L2-friendly supertile rasterization (groups of 8 output-row blocks)
    int bx = blockIdx.x, by = blockIdx.y;
    if ((gridDim.y & 7) == 0) {
        int lin = by * gridDim.x + bx;
        int seg = gridDim.x * 8;
        int band = lin / seg, rem = lin % seg;
        by = band * 8 + (rem & 7);
        bx = rem >> 3;
    }

    size_t rowbase = (size_t)by * 128;
    int batch = rpbA ? (int)(rowbase / (size_t)rpbA) : 0;
    const __half* As  = Ah + rowbase * K;
    const __half* Als = Al + rowbase * K;
    const __half* Bs  = Bh + (size_t)batch * bstrB + (size_t)bx * TN * K;
    const __half* Bls = Bl + (size_t)batch * bstrB + (size_t)bx * TN * K;
    const int nch = K >> 6;

    auto load_chunk = [&](int c, int s) {
        uint32_t st = t0 + s * STAGE;
        int k0 = c << 6;
        #pragma unroll
        for (int u = tid; u < 1024; u += 256) {
            int r = u >> 3, cc = u & 7;
            uint32_t d = st + SWZ(r * 128 + cc * 16);
            size_t  o = (size_t)r * K + k0 + cc * 8;
            cp16(d, As + o);
            if (TERMS == 3) cp16(d + OFF_AL, Als + o);
        }
        #pragma unroll
        for (int u = tid; u < TN * 8; u += 256) {
            int r = u >> 3, cc = u & 7;
            uint32_t d = st + OFF_BH + SWZ(r * 128 + cc * 16);
            size_t  o = (size_t)r * K + k0 + cc * 8;
            cp16(d, Bs + o);
            cp16(d + BB, Bls + o);
        }
    };

    for (int p = 0; p < NP; ++p) { if (p < nch) load_chunk(p, p); CP_COMMIT(); }

    float acc[2][JN][4] = {};
    int wm = (wid & 3) * 32, wn = (wid >> 2) * (TN / 2);
    int arow = lane & 15, aksel = (lane >> 4) * 16;
    int brow = (lane & 7) + ((lane >> 4) & 1) * 8, bksel = ((lane >> 3) & 1) * 16;

    for (int c = 0; c < nch; ++c) {
        if (TERMS == 3) asm volatile("cp.async.wait_group 2;\n" ::: "memory");
        else            asm volatile("cp.async.wait_group 1;\n" ::: "memory");
        __syncthreads();
        if (c + NP < nch) load_chunk(c + NP, (c + NP) % NS);
        CP_COMMIT();
        uint32_t ab = t0 + (c % NS) * STAGE;
        #pragma unroll
        for (int kk = 0; kk < 4; ++kk) {
            uint32_t ahf[2][4], alf[2][4], bhf[BF][4], blf[BF][4];
            #pragma unroll
            for (int i = 0; i < 2; ++i) {
                uint32_t off = SWZ((wm + i * 16 + arow) * 128 + kk * 32 + aksel);
                ldsm4(ahf[i], ab + off);
                if (TERMS == 3) ldsm4(alf[i], ab + OFF_AL + off);
            }
            #pragma unroll
            for (int jf = 0; jf < BF; ++jf) {
                uint32_t off = SWZ((wn + jf * 16 + brow) * 128 + kk * 32 + bksel);
                ldsm4(bhf[jf], ab + OFF_BH + off);
                ldsm4(blf[jf], ab + OFF_BL + off);
            }
            #pragma unroll
            for (int i = 0; i < 2; ++i)
                #pragma unroll
                for (int j = 0; j < JN; ++j) {
                    const uint32_t* bh2 = &bhf[j >> 1][(j & 1) * 2];
                    const uint32_t* bl2 = &blf[j >> 1][(j & 1) * 2];
                    mma(acc[i][j], ahf[i], bh2);
                    mma(acc[i][j], ahf[i], bl2);
                    if (TERMS == 3) mma(acc[i][j], alf[i], bh2);
                }
        }
    }

    int r0l = lane >> 2, cpair = (lane & 3) * 2;
    #pragma unroll
    for (int i = 0; i < 2; ++i)
        #pragma unroll
        for (int j = 0; j < JN; ++j) {
            int colg = bx * TN + wn + j * 8 + cpair;
            #pragma unroll
            for (int hh2 = 0; hh2 < 2; ++hh2) {
                size_t rowg = rowbase + wm + i * 16 + r0l + hh2 * 8;
                float v0 = acc[i][j][hh2 * 2], v1 = acc[i][j][hh2 * 2 + 1];
                if (MODE == 0) {
                    *(float2*)&Cf[rowg * (size_t)ldn + colg] = make_float2(v0, v1);
                } else if (MODE == 1) {
                    float2* p = (float2*)&Cf[rowg * (size_t)ldn + colg];
                    float2 o = *p; o.x += v0; o.y += v1; *p = o;
                } else if (MODE == 3) {          // Q: scale -> hi only [b,h,i,d]
                    int b = (int)(rowg >> 11), ii = (int)(rowg & 2047);
                    int hd = colg >> 6, d = colg & 63;
                    size_t o = (((size_t)b * HEADS + hd) * NQ + ii) * DHEAD + d;
                    *(half2*)&g_Qh[o] = __floats2half2_rn(v0 * 0.125f, v1 * 0.125f);
                } else if (MODE == 4) {          // KV split: K[b,j,d], Vt[b,d,j]
                    __half h0 = __float2half_rn(v0), h1 = __float2half_rn(v1);
                    int b = (int)(rowg >> 10), jj = (int)(rowg & 1023);
                    if (colg < 64) {
                        size_t o = ((size_t)b * NCTX + jj) * DHEAD + colg;
                        *(half2*)&g_Kh[o] = __halves2half2(h0, h1);
                        *(half2*)&g_Kl[o] = __halves2half2(
                            __float2half_rn(v0 - __half2float(h0)),
                            __float2half_rn(v1 - __half2float(h1)));
                    } else {
                        int d0 = colg - 64;
                        g_Vth[((size_t)b * DHEAD + d0) * NCTX + jj] = h0;
                        g_Vth[((size_t)b * DHEAD + d0 + 1) * NCTX + jj] = h1;
                    }
                } else if (MODE == 6) {          // FF1 interleaved -> silu (hi)
                    int m = colg >> 1;           // v0 = h, v1 = gate
                    float a = (v1 / (1.f + __expf(-v1))) * v0;
                    g_ah[rowg * (size_t)FFI + m] = __float2half_rn(a);
                }
            }
        }
}

// ------------------------- fused flash attention --------------------------
// Q hi [b,h,i,d]; K split [b,j,d]; Vt plain [b,d,j]. Output att hi only.
__global__ void __launch_bounds__(256, 2) flash_attn(
    const __half* __restrict__ Qh,
    const __half* __restrict__ Kh, const __half* __restrict__ Kl,
    const __half* __restrict__ Vt, __half* __restrict__ atth)
{
    extern __shared__ char smem[];
    uint32_t t0 = smem_u32(smem);
    const uint32_t QHO = 0, ST0 = 16384, STSZ = 24576;
    int tid = threadIdx.x, lane = tid & 31, wid = tid >> 5;
    int bh = blockIdx.y, b = bh >> 4, h = bh & 15;
    int i0 = blockIdx.x * 128;
    const __half* Qhp = Qh + (((size_t)b * HEADS + h) * NQ + i0) * DHEAD;
    const __half* Khp = Kh + (size_t)b * NCTX * DHEAD;
    const __half* Klp = Kl + (size_t)b * NCTX * DHEAD;
    const __half* Vtp = Vt + (size_t)b * DHEAD * NCTX;

    for (int u = tid; u < 128 * 8; u += 256) {
        int r = u >> 3, c = u & 7;
        cp16(t0 + QHO + SWZ(r * 128 + c * 16), Qhp + (size_t)r * DHEAD + c * 8);
    }
    auto load_kv = [&](int t, int s) {
        uint32_t st = t0 + ST0 + s * STSZ;
        int j0 = t * 64;
        for (int u = tid; u < 64 * 8; u += 256) {
            int r = u >> 3, c = u & 7;
            uint32_t d = SWZ(r * 128 + c * 16);
            cp16(st + d,         Khp + (size_t)(j0 + r) * DHEAD + c * 8);
            cp16(st + 8192 + d,  Klp + (size_t)(j0 + r) * DHEAD + c * 8);
            cp16(st + 16384 + d, Vtp + (size_t)r * NCTX + j0 + c * 8);
        }
    };
    load_kv(0, 0);
    CP_COMMIT();

    float acc_o[8][4] = {};
    float mrow0 = -1e30f, mrow1 = -1e30f, lrow0 = 0.f, lrow1 = 0.f;
    int wm = wid * 16;
    int arow = lane & 15, aksel = (lane >> 4) * 16;
    int brow = (lane & 7) + ((lane >> 4) & 1) * 8, bksel = ((lane >> 3) & 1) * 16;

    for (int t = 0; t < 16; ++t) {
        CP_WAIT0();
        __syncthreads();
        if (t + 1 < 16) load_kv(t + 1, (t + 1) & 1);
        CP_COMMIT();
        uint32_t st = t0 + ST0 + (t & 1) * STSZ;

        // S = Q K^T  (2-term: Qh*Kh + Qh*Kl)
        float s[8][4] = {};
        #pragma unroll
        for (int kk = 0; kk < 4; ++kk) {
            uint32_t ahf[4];
            ldsm4(ahf, t0 + QHO + SWZ((wm + arow) * 128 + kk * 32 + aksel));
            #pragma unroll
            for (int jf = 0; jf < 4; ++jf) {
                uint32_t bhf[4], blf[4];
                uint32_t offb = SWZ((jf * 16 + brow) * 128 + kk * 32 + bksel);
                ldsm4(bhf, st + offb);
                ldsm4(blf, st + 8192 + offb);
                #pragma unroll
                for (int hf = 0; hf < 2; ++hf) {
                    int nf = jf * 2 + hf;
                    mma(s[nf], ahf, &bhf[hf * 2]);
                    mma(s[nf], ahf, &blf[hf * 2]);
                }
            }
        }

        float mx0 = mrow0, mx1 = mrow1;
        #pragma unroll
        for (int nf = 0; nf < 8; ++nf) {
            mx0 = fmaxf(mx0, fmaxf(s[nf][0], s[nf][1]));
            mx1 = fmaxf(mx1, fmaxf(s[nf][2], s[nf][3]));
        }
        mx0 = fmaxf(mx0, __shfl_xor_sync(~0u, mx0, 1));
        mx0 = fmaxf(mx0, __shfl_xor_sync(~0u, mx0, 2));
        mx1 = fmaxf(mx1, __shfl_xor_sync(~0u, mx1, 1));
        mx1 = fmaxf(mx1, __shfl_xor_sync(~0u, mx1, 2));
        float corr0 = __expf(mrow0 - mx0), corr1 = __expf(mrow1 - mx1);
        mrow0 = mx0; mrow1 = mx1;
        float sum0 = 0.f, sum1 = 0.f;
        #pragma unroll
        for (int nf = 0; nf < 8; ++nf) {
            s[nf][0] = __expf(s[nf][0] - mx0); s[nf][1] = __expf(s[nf][1] - mx0);
            s[nf][2] = __expf(s[nf][2] - mx1); s[nf][3] = __expf(s[nf][3] - mx1);
            sum0 += s[nf][0] + s[nf][1]; sum1 += s[nf][2] + s[nf][3];
        }
        sum0 += __shfl_xor_sync(~0u, sum0, 1); sum0 += __shfl_xor_sync(~0u, sum0, 2);
        sum1 += __shfl_xor_sync(~0u, sum1, 1); sum1 += __shfl_xor_sync(~0u, sum1, 2);
        lrow0 = lrow0 * corr0 + sum0;
        lrow1 = lrow1 * corr1 + sum1;
        #pragma unroll
        for (int nf = 0; nf < 8; ++nf) {
            acc_o[nf][0] *= corr0; acc_o[nf][1] *= corr0;
            acc_o[nf][2] *= corr1; acc_o[nf][3] *= corr1;
        }

        uint32_t aph[4][4], apl[4][4];
        #pragma unroll
        for (int kf = 0; kf < 4; ++kf)
            #pragma unroll
            for (int q = 0; q < 4; ++q) {
                int nf = kf * 2 + (q >> 1), base = (q & 1) * 2;
                float v0 = s[nf][base], v1 = s[nf][base + 1];
                __half p0 = __float2half_rn(v0), p1 = __float2half_rn(v1);
                half2 hp = __halves2half2(p0, p1);
                aph[kf][q] = *(uint32_t*)&hp;
                half2 lp = __halves2half2(__float2half_rn(v0 - __half2float(p0)),
                                          __float2half_rn(v1 - __half2float(p1)));
                apl[kf][q] = *(uint32_t*)&lp;
            }

        #pragma unroll
        for (int kf = 0; kf < 4; ++kf)
            #pragma unroll
            for (int df = 0; df < 4; ++df) {
                uint32_t bv[4];
                ldsm4(bv, st + 16384 + SWZ((df * 16 + brow) * 128 + kf * 32 + bksel));
                #pragma unroll
                for (int hf = 0; hf < 2; ++hf) {
                    int nf = df * 2 + hf;
                    mma(acc_o[nf], aph[kf], &bv[hf * 2]);
                    mma(acc_o[nf], apl[kf], &bv[hf * 2]);
                }
            }
    }

    float inv0 = 1.f / lrow0, inv1 = 1.f / lrow1;
    int r0 = wm + (lane >> 2), cpair = (lane & 3) * 2;
    #pragma unroll
    for (int nf = 0; nf < 8; ++nf) {
        int d = nf * 8 + cpair;
        size_t o0 = ((size_t)b * NQ + (i0 + r0)) * DIMM + h * DHEAD + d;
        size_t o1 = ((size_t)b * NQ + (i0 + r0 + 8)) * DIMM + h * DHEAD + d;
        *(half2*)&atth[o0] = __floats2half2_rn(acc_o[nf][0] * inv0, acc_o[nf][1] * inv0);
        *(half2*)&atth[o1] = __floats2half2_rn(acc_o[nf][2] * inv1, acc_o[nf][3] * inv1);
    }
}

// ------------------------- LayerNorm -> split fp16 ------------------------
__global__ __launch_bounds__(256) void ln_split(
    const float* __restrict__ x, const float* __restrict__ g,
    const float* __restrict__ b, __half* __restrict__ yh, __half* __restrict__ yl)
{
    int row = blockIdx.x;
    const float* xr = x + (size_t)row * DIMM;
    float s = 0.f, s2 = 0.f;
    for (int c = threadIdx.x; c < DIMM; c += 256) { float v = xr[c]; s += v; s2 += v * v; }
    __shared__ float red[64];
    #pragma unroll
    for (int o = 16; o; o >>= 1) {
        s += __shfl_xor_sync(~0u, s, o); s2 += __shfl_xor_sync(~0u, s2, o);
    }
    int w = threadIdx.x >> 5, l = threadIdx.x & 31;
    if (l == 0) { red[w] = s; red[32 + w] = s2; }
    __syncthreads();
    if (w == 0) {
        s = (l < 8) ? red[l] : 0.f; s2 = (l < 8) ? red[32 + l] : 0.f;
        #pragma unroll
        for (int o = 4; o; o >>= 1) {
            s += __shfl_xor_sync(~0u, s, o); s2 += __shfl_xor_sync(~0u, s2, o);
        }
        if (l == 0) { red[0] = s; red[1] = s2; }
    }
    __syncthreads();
    float mu = red[0] / DIMM, var = red[1] / DIMM - mu * mu, inv = rsqrtf(var + 1e-5f);
    for (int c = threadIdx.x; c < DIMM; c += 256) {
        float v = (xr[c] - mu) * inv * g[c] + b[c];
        __half h = __float2half_rn(v);
        yh[(size_t)row * DIMM + c] = h;
        yl[(size_t)row * DIMM + c] = __float2half_rn(v - __half2float(h));
    }
}

// ------------------------- W[K,N] -> split transposed [N,K] ---------------
__global__ __launch_bounds__(256) void wsplit(
    const float* __restrict__ W, __half* __restrict__ Bh, __half* __restrict__ Bl,
    int K, int N, int ilv)
{
    __shared__ float t[32][33];
    int n0 = blockIdx.x * 32, k0 = blockIdx.y * 32;
    int tx = threadIdx.x & 31, ty = threadIdx.x >> 5;
    #pragma unroll
    for (int r = 0; r < 32; r += 8)
        t[ty + r][tx] = W[(size_t)(k0 + ty + r) * N + n0 + tx];
    __syncthreads();
    #pragma unroll
    for (int r = 0; r < 32; r += 8) {
        float v = t[tx][ty + r];
        __half h = __float2half_rn(v);
        int n = n0 + ty + r;
        int nd = ilv ? ((n < (N >> 1)) ? (n * 2) : ((n - (N >> 1)) * 2 + 1)) : n;
        size_t o = (size_t)nd * K + k0 + tx;
        Bh[o] = h; Bl[o] = __float2half_rn(v - __half2float(h));
    }
}

// ------------------------- launch -----------------------------------------
static void* sym(const void* s) { void* p = 0; cudaGetSymbolAddress(&p, s); return p; }

extern "C" void kernel_launch(void* const* d_in, const int* in_sizes, int n_in,
                              void* d_out, int out_size)
{
    const float* x    = (const float*)d_in[0];
    const float* ctx  = (const float*)d_in[1];
    const float* lng  = (const float*)d_in[2];
    const float* lnb  = (const float*)d_in[3];
    const float* clng = (const float*)d_in[4];
    const float* clnb = (const float*)d_in[5];
    const float* Wq   = (const float*)d_in[6];
    const float* Wkv  = (const float*)d_in[7];
    const float* Wo   = (const float*)d_in[8];
    const float* Wff1 = (const float*)d_in[9];
    const float* Wff2 = (const float*)d_in[10];
    float* out = (float*)d_out;

    __half *xnh = (__half*)sym(g_xnh), *xnl = (__half*)sym(g_xnl);
    __half *cnh = (__half*)sym(g_cnh), *cnl = (__half*)sym(g_cnl);
    __half *Qh = (__half*)sym(g_Qh);
    __half *Kh = (__half*)sym(g_Kh), *Kl = (__half*)sym(g_Kl);
    __half *Vt = (__half*)sym(g_Vth);
    __half *atth = (__half*)sym(g_atth);
    __half *ah = (__half*)sym(g_ah);
    __half *Wqh = (__half*)sym(g_Wqh), *Wql = (__half*)sym(g_Wql);
    __half *Wkh = (__half*)sym(g_Wkh), *Wkl = (__half*)sym(g_Wkl);
    __half *Woh = (__half*)sym(g_Woh), *Wol = (__half*)sym(g_Wol);
    __half *W1h = (__half*)sym(g_W1h), *W1l = (__half*)sym(g_W1l);
    __half *W2h = (__half*)sym(g_W2h), *W2l = (__half*)sym(g_W2l);

    const int SMEM3  = 4 * 49152;          // 192 KB (3-term, TN=64)
    const int SMEM2W = 3 * 49152;          // 144 KB (2-term, TN=128)
    const int FSMEM  = 16384 + 2 * 24576;  //  64 KB flash
    cudaFuncSetAttribute(gemm_hs<0,2,128>, cudaFuncAttributeMaxDynamicSharedMemorySize, SMEM2W);
    cudaFuncSetAttribute(gemm_hs<3,2,128>, cudaFuncAttributeMaxDynamicSharedMemorySize, SMEM2W);
    cudaFuncSetAttribute(gemm_hs<4,3,64>,  cudaFuncAttributeMaxDynamicSharedMemorySize, SMEM3);
    cudaFuncSetAttribute(gemm_hs<6,2,128>, cudaFuncAttributeMaxDynamicSharedMemorySize, SMEM2W);
    cudaFuncSetAttribute(gemm_hs<1,2,128>, cudaFuncAttributeMaxDynamicSharedMemorySize, SMEM2W);
    cudaFuncSetAttribute(flash_attn, cudaFuncAttributeMaxDynamicSharedMemorySize, FSMEM);

    // weight prep
    wsplit<<<dim3(DIMM/32, DIMM/32), 256>>>(Wq,   Wqh, Wql, DIMM, DIMM, 0);
    wsplit<<<dim3(128/32,  DIMM/32), 256>>>(Wkv,  Wkh, Wkl, DIMM, 128,  0);
    wsplit<<<dim3(DIMM/32, DIMM/32), 256>>>(Wo,   Woh, Wol, DIMM, DIMM, 0);
    wsplit<<<dim3(8192/32, DIMM/32), 256>>>(Wff1, W1h, W1l, DIMM, 8192, 1);
    wsplit<<<dim3(DIMM/32, FFI/32),  256>>>(Wff2, W2h, W2l, FFI,  DIMM, 0);

    // layernorms -> split
    ln_split<<<BATCH*NQ,   256>>>(x,   lng,  lnb,  xnh, xnl);
    ln_split<<<BATCH*NCTX, 256>>>(ctx, clng, clnb, cnh, cnl);

    // Q = xn@Wq (scale fused) -> hi [b,h,i,d]      (2-term, TN=128)
    gemm_hs<3,2,128><<<dim3(8, 64), 256, SMEM2W>>>(xnh, xnh, Wqh, Wql, 0, DIMM, DIMM, 0, 0);
    // KV = cn@Wkv -> K split, Vt plain             (3-term, TN=64)
    gemm_hs<4,3,64><<<dim3(2, 32), 256, SMEM3>>>(cnh, cnl, Wkh, Wkl, 0, DIMM, 128, 0, 0);
    // fused attention -> att hi [b,i,h*64+d]
    flash_attn<<<dim3(NQ/128, BATCH*HEADS), 256, FSMEM>>>(Qh, Kh, Kl, Vt, atth);
    // FF1 (interleaved) -> silu -> act hi          (2-term, TN=128)
    gemm_hs<6,2,128><<<dim3(64, 64), 256, SMEM2W>>>(xnh, xnh, W1h, W1l, 0, DIMM, 8192, 0, 0);
    // out = att@Wo                                 (2-term, TN=128)
    gemm_hs<0,2,128><<<dim3(8, 64), 256, SMEM2W>>>(atth, atth, Woh, Wol, out, DIMM, DIMM, 0, 0);
    // out += act@Wff2                              (2-term, TN=128)
    gemm_hs<1,2,128><<<dim3(8, 64), 256, SMEM2W>>>(ah, ah, W2h, W2l, out, FFI, DIMM, 0, 0);
}

// round 9
// speedup vs baseline: 1.6816x; 1.6816x over previous
#include <cuda_runtime.h>
#include <cuda_fp16.h>
#include <math.h>
#include <stdint.h>

#define BATCH 4
#define NQ    2048
#define NCTX  1024
#define DIMM  1024
#define HEADS 16
#define DHEAD 64
#define FFI   4096

// ------------------------- static scratch ---------------------------------
__device__ __align__(1024) __half g_xnh [(size_t)BATCH*NQ*DIMM];
__device__ __align__(1024) __half g_cnh [(size_t)BATCH*NCTX*DIMM];
__device__ __align__(1024) __half g_cnl [(size_t)BATCH*NCTX*DIMM];
__device__ __align__(1024) __half g_Qh  [(size_t)BATCH*HEADS*NQ*DHEAD];
__device__ __align__(1024) __half g_Kh  [(size_t)BATCH*NCTX*DHEAD];
__device__ __align__(1024) __half g_Kl  [(size_t)BATCH*NCTX*DHEAD];
__device__ __align__(1024) __half g_Vth [(size_t)BATCH*DHEAD*NCTX];
__device__ __align__(1024) __half g_atth[(size_t)BATCH*NQ*DIMM];
__device__ __align__(1024) __half g_ah  [(size_t)BATCH*NQ*FFI];
__device__ __align__(1024) __half g_Wqh [(size_t)DIMM*DIMM];
__device__ __align__(1024) __half g_Wkh [(size_t)2*DHEAD*DIMM];
__device__ __align__(1024) __half g_Wkl [(size_t)2*DHEAD*DIMM];
__device__ __align__(1024) __half g_Woh [(size_t)DIMM*DIMM];
__device__ __align__(1024) __half g_W1h [(size_t)2*FFI*DIMM];
__device__ __align__(1024) __half g_W2h [(size_t)DIMM*FFI];

// ------------------------- helpers ----------------------------------------
__device__ __forceinline__ uint32_t smem_u32(const void* p) {
    uint32_t a;
    asm("{ .reg .u64 t; cvta.to.shared.u64 t, %1; cvt.u32.u64 %0, t; }" : "=r"(a) : "l"(p));
    return a;
}
#define SWZ(x) ((x) ^ (((x) >> 3) & 0x70))
__device__ __forceinline__ void cp16(uint32_t dst, const void* src) {
    asm volatile("cp.async.cg.shared.global [%0], [%1], 16;\n" :: "r"(dst), "l"(src));
}
#define CP_COMMIT() asm volatile("cp.async.commit_group;\n" ::: "memory")
#define CP_WAIT0()  asm volatile("cp.async.wait_group 0;\n"  ::: "memory")
__device__ __forceinline__ void ldsm4(uint32_t* r, uint32_t a) {
    asm volatile("ldmatrix.sync.aligned.m8n8.x4.shared.b16 {%0,%1,%2,%3}, [%4];"
                 : "=r"(r[0]), "=r"(r[1]), "=r"(r[2]), "=r"(r[3]) : "r"(a));
}
__device__ __forceinline__ void mma(float* c, const uint32_t* a, const uint32_t* b) {
    asm volatile("mma.sync.aligned.m16n8k16.row.col.f32.f16.f16.f32 "
                 "{%0,%1,%2,%3}, {%4,%5,%6,%7}, {%8,%9}, {%0,%1,%2,%3};"
                 : "+f"(c[0]), "+f"(c[1]), "+f"(c[2]), "+f"(c[3])
                 : "r"(a[0]), "r"(a[1]), "r"(a[2]), "r"(a[3]), "r"(b[0]), "r"(b[1]));
}

// ------------------------- GEMM (HMMA) -------------------------------------
// C[M x Ntot] = A[M,K] @ B[N,K]^T ; BM=128, BN=TN, BK=64, 8 warps.
// TERMS=1: AhBh                (TN=128: 3x32KB, 2 CTA/SM)
// TERMS=2: AhBh+AhBl           (TN=64:  3x32KB, 2 CTA/SM)
// TERMS=3: AhBh+AhBl+AlBh      (TN=64:  4x48KB, 1 CTA/SM)
// MODE: 0 f32 store, 1 f32 add, 3 Q-hi(scale), 4 KV-split, 6 ff-silu
template <int MODE, int TERMS, int TN>
__global__ void __launch_bounds__(256, (TERMS == 3) ? 1 : 2) gemm_hs(
    const __half* __restrict__ Ah, const __half* __restrict__ Al,
    const __half* __restrict__ Bh, const __half* __restrict__ Bl,
    float* __restrict__ Cf, int K, int ldn, int rpbA, size_t bstrB)
{
    constexpr int TA     = (TERMS == 3) ? 2 : 1;
    constexpr int TB     = (TERMS >= 2) ? 2 : 1;
    constexpr int OFF_AL = 16384;
    constexpr int OFF_BH = 16384 * TA;
    constexpr int BB     = TN * 128;
    constexpr int OFF_BL = OFF_BH + BB;
    constexpr int STAGE  = OFF_BH + BB * TB;
    constexpr int NS     = (TERMS == 3) ? 4 : 3;
    constexpr int NP     = NS - 1;
    constexpr int JN     = TN / 16;
    constexpr int BF     = JN / 2;
    extern __shared__ char smem[];
    uint32_t t0 = smem_u32(smem);
    int tid = threadIdx.x, lane = tid & 31, wid = tid >> 5;

    // L2-friendly supertile rasterization (groups of 8 output-row blocks)
    int bx = blockIdx.x, by = blockIdx.y;
    if ((gridDim.y & 7) == 0) {
        int lin = by * gridDim.x + bx;
        int seg = gridDim.x * 8;
        int band = lin / seg, rem = lin % seg;
        by = band * 8 + (rem & 7);
        bx = rem >> 3;
    }

    size_t rowbase = (size_t)by * 128;
    int batch = rpbA ? (int)(rowbase / (size_t)rpbA) : 0;
    const __half* As  = Ah + rowbase * K;
    const __half* Als = Al + rowbase * K;
    const __half* Bs  = Bh + (size_t)batch * bstrB + (size_t)bx * TN * K;
    const __half* Bls = Bl + (size_t)batch * bstrB + (size_t)bx * TN * K;
    const int nch = K >> 6;

    auto load_chunk = [&](int c, int s) {
        uint32_t st = t0 + s * STAGE;
        int k0 = c << 6;
        #pragma unroll
        for (int u = tid; u < 1024; u += 256) {
            int r = u >> 3, cc = u & 7;
            uint32_t d = st + SWZ(r * 128 + cc * 16);
            size_t  o = (size_t)r * K + k0 + cc * 8;
            cp16(d, As + o);
            if (TERMS == 3) cp16(d + OFF_AL, Als + o);
        }
        #pragma unroll
        for (int u = tid; u < TN * 8; u += 256) {
            int r = u >> 3, cc = u & 7;
            uint32_t d = st + OFF_BH + SWZ(r * 128 + cc * 16);
            size_t  o = (size_t)r * K + k0 + cc * 8;
            cp16(d, Bs + o);
            if (TERMS >= 2) cp16(d + BB, Bls + o);
        }
    };

    for (int p = 0; p < NP; ++p) { if (p < nch) load_chunk(p, p); CP_COMMIT(); }

    float acc[2][JN][4] = {};
    int wm = (wid & 3) * 32, wn = (wid >> 2) * (TN / 2);
    int arow = lane & 15, aksel = (lane >> 4) * 16;
    int brow = (lane & 7) + ((lane >> 4) & 1) * 8, bksel = ((lane >> 3) & 1) * 16;

    for (int c = 0; c < nch; ++c) {
        asm volatile("cp.async.wait_group %0;\n" :: "n"(NS - 2) : "memory");
        __syncthreads();
        if (c + NP < nch) load_chunk(c + NP, (c + NP) % NS);
        CP_COMMIT();
        uint32_t ab = t0 + (c % NS) * STAGE;
        #pragma unroll
        for (int kk = 0; kk < 4; ++kk) {
            uint32_t ahf[2][4], alf[2][4], bhf[BF][4], blf[BF][4];
            #pragma unroll
            for (int i = 0; i < 2; ++i) {
                uint32_t off = SWZ((wm + i * 16 + arow) * 128 + kk * 32 + aksel);
                ldsm4(ahf[i], ab + off);
                if (TERMS == 3) ldsm4(alf[i], ab + OFF_AL + off);
            }
            #pragma unroll
            for (int jf = 0; jf < BF; ++jf) {
                uint32_t off = SWZ((wn + jf * 16 + brow) * 128 + kk * 32 + bksel);
                ldsm4(bhf[jf], ab + OFF_BH + off);
                if (TERMS >= 2) ldsm4(blf[jf], ab + OFF_BL + off);
            }
            #pragma unroll
            for (int i = 0; i < 2; ++i)
                #pragma unroll
                for (int j = 0; j < JN; ++j) {
                    const uint32_t* bh2 = &bhf[j >> 1][(j & 1) * 2];
                    mma(acc[i][j], ahf[i], bh2);
                    if (TERMS >= 2) mma(acc[i][j], ahf[i], &blf[j >> 1][(j & 1) * 2]);
                    if (TERMS == 3) mma(acc[i][j], alf[i], bh2);
                }
        }
    }

    int r0l = lane >> 2, cpair = (lane & 3) * 2;
    #pragma unroll
    for (int i = 0; i < 2; ++i)
        #pragma unroll
        for (int j = 0; j < JN; ++j) {
            int colg = bx * TN + wn + j * 8 + cpair;
            #pragma unroll
            for (int hh2 = 0; hh2 < 2; ++hh2) {
                size_t rowg = rowbase + wm + i * 16 + r0l + hh2 * 8;
                float v0 = acc[i][j][hh2 * 2], v1 = acc[i][j][hh2 * 2 + 1];
                if (MODE == 0) {
                    *(float2*)&Cf[rowg * (size_t)ldn + colg] = make_float2(v0, v1);
                } else if (MODE == 1) {
                    float2* p = (float2*)&Cf[rowg * (size_t)ldn + colg];
                    float2 o = *p; o.x += v0; o.y += v1; *p = o;
                } else if (MODE == 3) {          // Q: scale -> hi only [b,h,i,d]
                    int b = (int)(rowg >> 11), ii = (int)(rowg & 2047);
                    int hd = colg >> 6, d = colg & 63;
                    size_t o = (((size_t)b * HEADS + hd) * NQ + ii) * DHEAD + d;
                    *(half2*)&g_Qh[o] = __floats2half2_rn(v0 * 0.125f, v1 * 0.125f);
                } else if (MODE == 4) {          // KV split: K[b,j,d], Vt[b,d,j]
                    __half h0 = __float2half_rn(v0), h1 = __float2half_rn(v1);
                    int b = (int)(rowg >> 10), jj = (int)(rowg & 1023);
                    if (colg < 64) {
                        size_t o = ((size_t)b * NCTX + jj) * DHEAD + colg;
                        *(half2*)&g_Kh[o] = __halves2half2(h0, h1);
                        *(half2*)&g_Kl[o] = __halves2half2(
                            __float2half_rn(v0 - __half2float(h0)),
                            __float2half_rn(v1 - __half2float(h1)));
                    } else {
                        int d0 = colg - 64;
                        g_Vth[((size_t)b * DHEAD + d0) * NCTX + jj] = h0;
                        g_Vth[((size_t)b * DHEAD + d0 + 1) * NCTX + jj] = h1;
                    }
                } else if (MODE == 6) {          // FF1 interleaved -> silu (hi)
                    int m = colg >> 1;           // v0 = h, v1 = gate
                    float a = (v1 / (1.f + __expf(-v1))) * v0;
                    g_ah[rowg * (size_t)FFI + m] = __float2half_rn(a);
                }
            }
        }
}

// ------------------------- fused flash attention --------------------------
// Q hi [b,h,i,d]; K split [b,j,d]; Vt plain [b,d,j]. Output att hi only.
__global__ void __launch_bounds__(256, 2) flash_attn(
    const __half* __restrict__ Qh,
    const __half* __restrict__ Kh, const __half* __restrict__ Kl,
    const __half* __restrict__ Vt, __half* __restrict__ atth)
{
    extern __shared__ char smem[];
    uint32_t t0 = smem_u32(smem);
    const uint32_t QHO = 0, ST0 = 16384, STSZ = 24576;
    int tid = threadIdx.x, lane = tid & 31, wid = tid >> 5;
    int bh = blockIdx.y, b = bh >> 4, h = bh & 15;
    int i0 = blockIdx.x * 128;
    const __half* Qhp = Qh + (((size_t)b * HEADS + h) * NQ + i0) * DHEAD;
    const __half* Khp = Kh + (size_t)b * NCTX * DHEAD;
    const __half* Klp = Kl + (size_t)b * NCTX * DHEAD;
    const __half* Vtp = Vt + (size_t)b * DHEAD * NCTX;

    for (int u = tid; u < 128 * 8; u += 256) {
        int r = u >> 3, c = u & 7;
        cp16(t0 + QHO + SWZ(r * 128 + c * 16), Qhp + (size_t)r * DHEAD + c * 8);
    }
    auto load_kv = [&](int t, int s) {
        uint32_t st = t0 + ST0 + s * STSZ;
        int j0 = t * 64;
        for (int u = tid; u < 64 * 8; u += 256) {
            int r = u >> 3, c = u & 7;
            uint32_t d = SWZ(r * 128 + c * 16);
            cp16(st + d,         Khp + (size_t)(j0 + r) * DHEAD + c * 8);
            cp16(st + 8192 + d,  Klp + (size_t)(j0 + r) * DHEAD + c * 8);
            cp16(st + 16384 + d, Vtp + (size_t)r * NCTX + j0 + c * 8);
        }
    };
    load_kv(0, 0);
    CP_COMMIT();

    float acc_o[8][4] = {};
    float mrow0 = -1e30f, mrow1 = -1e30f, lrow0 = 0.f, lrow1 = 0.f;
    int wm = wid * 16;
    int arow = lane & 15, aksel = (lane >> 4) * 16;
    int brow = (lane & 7) + ((lane >> 4) & 1) * 8, bksel = ((lane >> 3) & 1) * 16;

    for (int t = 0; t < 16; ++t) {
        CP_WAIT0();
        __syncthreads();
        if (t + 1 < 16) load_kv(t + 1, (t + 1) & 1);
        CP_COMMIT();
        uint32_t st = t0 + ST0 + (t & 1) * STSZ;

        // S = Q K^T  (2-term: Qh*Kh + Qh*Kl)
        float s[8][4] = {};
        #pragma unroll
        for (int kk = 0; kk < 4; ++kk) {
            uint32_t ahf[4];
            ldsm4(ahf, t0 + QHO + SWZ((wm + arow) * 128 + kk * 32 + aksel));
            #pragma unroll
            for (int jf = 0; jf < 4; ++jf) {
                uint32_t bhf[4], blf[4];
                uint32_t offb = SWZ((jf * 16 + brow) * 128 + kk * 32 + bksel);
                ldsm4(bhf, st + offb);
                ldsm4(blf, st + 8192 + offb);
                #pragma unroll
                for (int hf = 0; hf < 2; ++hf) {
                    int nf = jf * 2 + hf;
                    mma(s[nf], ahf, &bhf[hf * 2]);
                    mma(s[nf], ahf, &blf[hf * 2]);
                }
            }
        }

        float mx0 = mrow0, mx1 = mrow1;
        #pragma unroll
        for (int nf = 0; nf < 8; ++nf) {
            mx0 = fmaxf(mx0, fmaxf(s[nf][0], s[nf][1]));
            mx1 = fmaxf(mx1, fmaxf(s[nf][2], s[nf][3]));
        }
        mx0 = fmaxf(mx0, __shfl_xor_sync(~0u, mx0, 1));
        mx0 = fmaxf(mx0, __shfl_xor_sync(~0u, mx0, 2));
        mx1 = fmaxf(mx1, __shfl_xor_sync(~0u, mx1, 1));
        mx1 = fmaxf(mx1, __shfl_xor_sync(~0u, mx1, 2));
        float corr0 = __expf(mrow0 - mx0), corr1 = __expf(mrow1 - mx1);
        mrow0 = mx0; mrow1 = mx1;
        float sum0 = 0.f, sum1 = 0.f;
        #pragma unroll
        for (int nf = 0; nf < 8; ++nf) {
            s[nf][0] = __expf(s[nf][0] - mx0); s[nf][1] = __expf(s[nf][1] - mx0);
            s[nf][2] = __expf(s[nf][2] - mx1); s[nf][3] = __expf(s[nf][3] - mx1);
            sum0 += s[nf][0] + s[nf][1]; sum1 += s[nf][2] + s[nf][3];
        }
        sum0 += __shfl_xor_sync(~0u, sum0, 1); sum0 += __shfl_xor_sync(~0u, sum0, 2);
        sum1 += __shfl_xor_sync(~0u, sum1, 1); sum1 += __shfl_xor_sync(~0u, sum1, 2);
        lrow0 = lrow0 * corr0 + sum0;
        lrow1 = lrow1 * corr1 + sum1;
        #pragma unroll
        for (int nf = 0; nf < 8; ++nf) {
            acc_o[nf][0] *= corr0; acc_o[nf][1] *= corr0;
            acc_o[nf][2] *= corr1; acc_o[nf][3] *= corr1;
        }

        uint32_t aph[4][4], apl[4][4];
        #pragma unroll
        for (int kf = 0; kf < 4; ++kf)
            #pragma unroll
            for (int q = 0; q < 4; ++q) {
                int nf = kf * 2 + (q >> 1), base = (q & 1) * 2;
                float v0 = s[nf][base], v1 = s[nf][base + 1];
                __half p0 = __float2half_rn(v0), p1 = __float2half_rn(v1);
                half2 hp = __halves2half2(p0, p1);
                aph[kf][q] = *(uint32_t*)&hp;
                half2 lp = __halves2half2(__float2half_rn(v0 - __half2float(p0)),
                                          __float2half_rn(v1 - __half2float(p1)));
                apl[kf][q] = *(uint32_t*)&lp;
            }

        #pragma unroll
        for (int kf = 0; kf < 4; ++kf)
            #pragma unroll
            for (int df = 0; df < 4; ++df) {
                uint32_t bv[4];
                ldsm4(bv, st + 16384 + SWZ((df * 16 + brow) * 128 + kf * 32 + bksel));
                #pragma unroll
                for (int hf = 0; hf < 2; ++hf) {
                    int nf = df * 2 + hf;
                    mma(acc_o[nf], aph[kf], &bv[hf * 2]);
                    mma(acc_o[nf], apl[kf], &bv[hf * 2]);
                }
            }
    }

    float inv0 = 1.f / lrow0, inv1 = 1.f / lrow1;
    int r0 = wm + (lane >> 2), cpair = (lane & 3) * 2;
    #pragma unroll
    for (int nf = 0; nf < 8; ++nf) {
        int d = nf * 8 + cpair;
        size_t o0 = ((size_t)b * NQ + (i0 + r0)) * DIMM + h * DHEAD + d;
        size_t o1 = ((size_t)b * NQ + (i0 + r0 + 8)) * DIMM + h * DHEAD + d;
        *(half2*)&atth[o0] = __floats2half2_rn(acc_o[nf][0] * inv0, acc_o[nf][1] * inv0);
        *(half2*)&atth[o1] = __floats2half2_rn(acc_o[nf][2] * inv1, acc_o[nf][3] * inv1);
    }
}

// ------------------------- LayerNorm -> fp16 (optional lo) ----------------
__global__ __launch_bounds__(256) void ln_split(
    const float* __restrict__ x, const float* __restrict__ g,
    const float* __restrict__ b, __half* __restrict__ yh, __half* __restrict__ yl)
{
    int row = blockIdx.x;
    const float* xr = x + (size_t)row * DIMM;
    float s = 0.f, s2 = 0.f;
    for (int c = threadIdx.x; c < DIMM; c += 256) { float v = xr[c]; s += v; s2 += v * v; }
    __shared__ float red[64];
    #pragma unroll
    for (int o = 16; o; o >>= 1) {
        s += __shfl_xor_sync(~0u, s, o); s2 += __shfl_xor_sync(~0u, s2, o);
    }
    int w = threadIdx.x >> 5, l = threadIdx.x & 31;
    if (l == 0) { red[w] = s; red[32 + w] = s2; }
    __syncthreads();
    if (w == 0) {
        s = (l < 8) ? red[l] : 0.f; s2 = (l < 8) ? red[32 + l] : 0.f;
        #pragma unroll
        for (int o = 4; o; o >>= 1) {
            s += __shfl_xor_sync(~0u, s, o); s2 += __shfl_xor_sync(~0u, s2, o);
        }
        if (l == 0) { red[0] = s; red[1] = s2; }
    }
    __syncthreads();
    float mu = red[0] / DIMM, var = red[1] / DIMM - mu * mu, inv = rsqrtf(var + 1e-5f);
    for (int c = threadIdx.x; c < DIMM; c += 256) {
        float v = (xr[c] - mu) * inv * g[c] + b[c];
        __half h = __float2half_rn(v);
        yh[(size_t)row * DIMM + c] = h;
        if (yl) yl[(size_t)row * DIMM + c] = __float2half_rn(v - __half2float(h));
    }
}

// ------------------------- W[K,N] -> transposed [N,K] (optional lo) -------
__global__ __launch_bounds__(256) void wsplit(
    const float* __restrict__ W, __half* __restrict__ Bh, __half* __restrict__ Bl,
    int K, int N, int ilv)
{
    __shared__ float t[32][33];
    int n0 = blockIdx.x * 32, k0 = blockIdx.y * 32;
    int tx = threadIdx.x & 31, ty = threadIdx.x >> 5;
    #pragma unroll
    for (int r = 0; r < 32; r += 8)
        t[ty + r][tx] = W[(size_t)(k0 + ty + r) * N + n0 + tx];
    __syncthreads();
    #pragma unroll
    for (int r = 0; r < 32; r += 8) {
        float v = t[tx][ty + r];
        __half h = __float2half_rn(v);
        int n = n0 + ty + r;
        int nd = ilv ? ((n < (N >> 1)) ? (n * 2) : ((n - (N >> 1)) * 2 + 1)) : n;
        size_t o = (size_t)nd * K + k0 + tx;
        Bh[o] = h;
        if (Bl) Bl[o] = __float2half_rn(v - __half2float(h));
    }
}

// ------------------------- launch -----------------------------------------
static void* sym(const void* s) { void* p = 0; cudaGetSymbolAddress(&p, s); return p; }

extern "C" void kernel_launch(void* const* d_in, const int* in_sizes, int n_in,
                              void* d_out, int out_size)
{
    const float* x    = (const float*)d_in[0];
    const float* ctx  = (const float*)d_in[1];
    const float* lng  = (const float*)d_in[2];
    const float* lnb  = (const float*)d_in[3];
    const float* clng = (const float*)d_in[4];
    const float* clnb = (const float*)d_in[5];
    const float* Wq   = (const float*)d_in[6];
    const float* Wkv  = (const float*)d_in[7];
    const float* Wo   = (const float*)d_in[8];
    const float* Wff1 = (const float*)d_in[9];
    const float* Wff2 = (const float*)d_in[10];
    float* out = (float*)d_out;

    __half *xnh = (__half*)sym(g_xnh);
    __half *cnh = (__half*)sym(g_cnh), *cnl = (__half*)sym(g_cnl);
    __half *Qh = (__half*)sym(g_Qh);
    __half *Kh = (__half*)sym(g_Kh), *Kl = (__half*)sym(g_Kl);
    __half *Vt = (__half*)sym(g_Vth);
    __half *atth = (__half*)sym(g_atth);
    __half *ah = (__half*)sym(g_ah);
    __half *Wqh = (__half*)sym(g_Wqh);
    __half *Wkh = (__half*)sym(g_Wkh), *Wkl = (__half*)sym(g_Wkl);
    __half *Woh = (__half*)sym(g_Woh);
    __half *W1h = (__half*)sym(g_W1h);
    __half *W2h = (__half*)sym(g_W2h);

    const int SMEM3  = 4 * 49152;          // 192 KB (3-term, TN=64)
    const int SMEM1  = 3 * 32768;          //  96 KB (1-term, TN=128)
    const int FSMEM  = 16384 + 2 * 24576;  //  64 KB flash
    cudaFuncSetAttribute(gemm_hs<0,1,128>, cudaFuncAttributeMaxDynamicSharedMemorySize, SMEM1);
    cudaFuncSetAttribute(gemm_hs<1,1,128>, cudaFuncAttributeMaxDynamicSharedMemorySize, SMEM1);
    cudaFuncSetAttribute(gemm_hs<3,1,128>, cudaFuncAttributeMaxDynamicSharedMemorySize, SMEM1);
    cudaFuncSetAttribute(gemm_hs<6,1,128>, cudaFuncAttributeMaxDynamicSharedMemorySize, SMEM1);
    cudaFuncSetAttribute(gemm_hs<4,3,64>,  cudaFuncAttributeMaxDynamicSharedMemorySize, SMEM3);
    cudaFuncSetAttribute(flash_attn, cudaFuncAttributeMaxDynamicSharedMemorySize, FSMEM);

    // weight prep (lo planes only where needed: Wkv)
    wsplit<<<dim3(DIMM/32, DIMM/32), 256>>>(Wq,   Wqh, 0,   DIMM, DIMM, 0);
    wsplit<<<dim3(128/32,  DIMM/32), 256>>>(Wkv,  Wkh, Wkl, DIMM, 128,  0);
    wsplit<<<dim3(DIMM/32, DIMM/32), 256>>>(Wo,   Woh, 0,   DIMM, DIMM, 0);
    wsplit<<<dim3(8192/32, DIMM/32), 256>>>(Wff1, W1h, 0,   DIMM, 8192, 1);
    wsplit<<<dim3(DIMM/32, FFI/32),  256>>>(Wff2, W2h, 0,   FFI,  DIMM, 0);

    // layernorms (x: hi only; ctx: split for 3-term KV)
    ln_split<<<BATCH*NQ,   256>>>(x,   lng,  lnb,  xnh, 0);
    ln_split<<<BATCH*NCTX, 256>>>(ctx, clng, clnb, cnh, cnl);

    // Q = xn@Wq (scale fused) -> hi [b,h,i,d]      (1-term, TN=128)
    gemm_hs<3,1,128><<<dim3(8, 64), 256, SMEM1>>>(xnh, xnh, Wqh, Wqh, 0, DIMM, DIMM, 0, 0);
    // KV = cn@Wkv -> K split, Vt plain             (3-term, TN=64)
    gemm_hs<4,3,64><<<dim3(2, 32), 256, SMEM3>>>(cnh, cnl, Wkh, Wkl, 0, DIMM, 128, 0, 0);
    // fused attention -> att hi [b,i,h*64+d]
    flash_attn<<<dim3(NQ/128, BATCH*HEADS), 256, FSMEM>>>(Qh, Kh, Kl, Vt, atth);
    // FF1 (interleaved) -> silu -> act hi          (1-term, TN=128)
    gemm_hs<6,1,128><<<dim3(64, 64), 256, SMEM1>>>(xnh, xnh, W1h, W1h, 0, DIMM, 8192, 0, 0);
    // out = att@Wo                                 (1-term, TN=128)
    gemm_hs<0,1,128><<<dim3(8, 64), 256, SMEM1>>>(atth, atth, Woh, Woh, out, DIMM, DIMM, 0, 0);
    // out += act@Wff2                              (1-term, TN=128)
    gemm_hs<1,1,128><<<dim3(8, 64), 256, SMEM1>>>(ah, ah, W2h, W2h, out, FFI, DIMM, 0, 0);
}

// round 10
// speedup vs baseline: 1.8349x; 1.0912x over previous
#include <cuda_runtime.h>
#include <cuda_fp16.h>
#include <math.h>
#include <stdint.h>

#define BATCH 4
#define NQ    2048
#define NCTX  1024
#define DIMM  1024
#define HEADS 16
#define DHEAD 64
#define FFI   4096
#define KCAT  5120   // 1024 (att) + 4096 (act)

// ------------------------- static scratch ---------------------------------
__device__ __align__(1024) __half g_xnh [(size_t)BATCH*NQ*DIMM];
__device__ __align__(1024) __half g_cnh [(size_t)BATCH*NCTX*DIMM];
__device__ __align__(1024) __half g_cnl [(size_t)BATCH*NCTX*DIMM];
__device__ __align__(1024) __half g_Qh  [(size_t)BATCH*HEADS*NQ*DHEAD];
__device__ __align__(1024) __half g_Kh  [(size_t)BATCH*NCTX*DHEAD];
__device__ __align__(1024) __half g_Vth [(size_t)BATCH*DHEAD*NCTX];
__device__ __align__(1024) __half g_cat [(size_t)BATCH*NQ*KCAT];   // [att | act]
__device__ __align__(1024) __half g_Wqh [(size_t)DIMM*DIMM];
__device__ __align__(1024) __half g_Wkh [(size_t)2*DHEAD*DIMM];
__device__ __align__(1024) __half g_Wkl [(size_t)2*DHEAD*DIMM];
__device__ __align__(1024) __half g_W1h [(size_t)2*FFI*DIMM];
__device__ __align__(1024) __half g_Wcat[(size_t)DIMM*KCAT];       // [Wo | Wff2] rows

// ------------------------- helpers ----------------------------------------
__device__ __forceinline__ uint32_t smem_u32(const void* p) {
    uint32_t a;
    asm("{ .reg .u64 t; cvta.to.shared.u64 t, %1; cvt.u32.u64 %0, t; }" : "=r"(a) : "l"(p));
    return a;
}
#define SWZ(x) ((x) ^ (((x) >> 3) & 0x70))
__device__ __forceinline__ void cp16(uint32_t dst, const void* src) {
    asm volatile("cp.async.cg.shared.global [%0], [%1], 16;\n" :: "r"(dst), "l"(src));
}
#define CP_COMMIT() asm volatile("cp.async.commit_group;\n" ::: "memory")
#define CP_WAIT0()  asm volatile("cp.async.wait_group 0;\n"  ::: "memory")
__device__ __forceinline__ void ldsm4(uint32_t* r, uint32_t a) {
    asm volatile("ldmatrix.sync.aligned.m8n8.x4.shared.b16 {%0,%1,%2,%3}, [%4];"
                 : "=r"(r[0]), "=r"(r[1]), "=r"(r[2]), "=r"(r[3]) : "r"(a));
}
__device__ __forceinline__ void mma(float* c, const uint32_t* a, const uint32_t* b) {
    asm volatile("mma.sync.aligned.m16n8k16.row.col.f32.f16.f16.f32 "
                 "{%0,%1,%2,%3}, {%4,%5,%6,%7}, {%8,%9}, {%0,%1,%2,%3};"
                 : "+f"(c[0]), "+f"(c[1]), "+f"(c[2]), "+f"(c[3])
                 : "r"(a[0]), "r"(a[1]), "r"(a[2]), "r"(a[3]), "r"(b[0]), "r"(b[1]));
}

// ------------------------- GEMM (HMMA) -------------------------------------
// C[M x Ntot] = A[M,K] @ B[N,K]^T ; BM=128, BN=TN, BK=64, 8 warps.
// TERMS=1: AhBh (TN=128: 3x32KB, 2 CTA/SM)  TERMS=3: +AhBl+AlBh (TN=64, 4 st)
// MODE: 0 f32 store, 3 Q-hi(scale), 4 KV, 6 ff-silu -> cat
template <int MODE, int TERMS, int TN>
__global__ void __launch_bounds__(256, (TERMS == 3) ? 1 : 2) gemm_hs(
    const __half* __restrict__ Ah, const __half* __restrict__ Al,
    const __half* __restrict__ Bh, const __half* __restrict__ Bl,
    float* __restrict__ Cf, int K, int ldn, int rpbA, size_t bstrB)
{
    constexpr int TA     = (TERMS == 3) ? 2 : 1;
    constexpr int TB     = (TERMS >= 2) ? 2 : 1;
    constexpr int OFF_AL = 16384;
    constexpr int OFF_BH = 16384 * TA;
    constexpr int BB     = TN * 128;
    constexpr int OFF_BL = OFF_BH + BB;
    constexpr int STAGE  = OFF_BH + BB * TB;
    constexpr int NS     = (TERMS == 3) ? 4 : 3;
    constexpr int NP     = NS - 1;
    constexpr int JN     = TN / 16;
    constexpr int BF     = JN / 2;
    extern __shared__ char smem[];
    uint32_t t0 = smem_u32(smem);
    int tid = threadIdx.x, lane = tid & 31, wid = tid >> 5;

    int bx = blockIdx.x, by = blockIdx.y;
    if ((gridDim.y & 7) == 0) {
        int lin = by * gridDim.x + bx;
        int seg = gridDim.x * 8;
        int band = lin / seg, rem = lin % seg;
        by = band * 8 + (rem & 7);
        bx = rem >> 3;
    }

    size_t rowbase = (size_t)by * 128;
    int batch = rpbA ? (int)(rowbase / (size_t)rpbA) : 0;
    const __half* As  = Ah + rowbase * K;
    const __half* Als = Al + rowbase * K;
    const __half* Bs  = Bh + (size_t)batch * bstrB + (size_t)bx * TN * K;
    const __half* Bls = Bl + (size_t)batch * bstrB + (size_t)bx * TN * K;
    const int nch = K >> 6;

    auto load_chunk = [&](int c, int s) {
        uint32_t st = t0 + s * STAGE;
        int k0 = c << 6;
        #pragma unroll
        for (int u = tid; u < 1024; u += 256) {
            int r = u >> 3, cc = u & 7;
            uint32_t d = st + SWZ(r * 128 + cc * 16);
            size_t  o = (size_t)r * K + k0 + cc * 8;
            cp16(d, As + o);
            if (TERMS == 3) cp16(d + OFF_AL, Als + o);
        }
        #pragma unroll
        for (int u = tid; u < TN * 8; u += 256) {
            int r = u >> 3, cc = u & 7;
            uint32_t d = st + OFF_BH + SWZ(r * 128 + cc * 16);
            size_t  o = (size_t)r * K + k0 + cc * 8;
            cp16(d, Bs + o);
            if (TERMS >= 2) cp16(d + BB, Bls + o);
        }
    };

    for (int p = 0; p < NP; ++p) { if (p < nch) load_chunk(p, p); CP_COMMIT(); }

    float acc[2][JN][4] = {};
    int wm = (wid & 3) * 32, wn = (wid >> 2) * (TN / 2);
    int arow = lane & 15, aksel = (lane >> 4) * 16;
    int brow = (lane & 7) + ((lane >> 4) & 1) * 8, bksel = ((lane >> 3) & 1) * 16;

    for (int c = 0; c < nch; ++c) {
        asm volatile("cp.async.wait_group %0;\n" :: "n"(NS - 2) : "memory");
        __syncthreads();
        if (c + NP < nch) load_chunk(c + NP, (c + NP) % NS);
        CP_COMMIT();
        uint32_t ab = t0 + (c % NS) * STAGE;
        #pragma unroll
        for (int kk = 0; kk < 4; ++kk) {
            uint32_t ahf[2][4], alf[2][4], bhf[BF][4], blf[BF][4];
            #pragma unroll
            for (int i = 0; i < 2; ++i) {
                uint32_t off = SWZ((wm + i * 16 + arow) * 128 + kk * 32 + aksel);
                ldsm4(ahf[i], ab + off);
                if (TERMS == 3) ldsm4(alf[i], ab + OFF_AL + off);
            }
            #pragma unroll
            for (int jf = 0; jf < BF; ++jf) {
                uint32_t off = SWZ((wn + jf * 16 + brow) * 128 + kk * 32 + bksel);
                ldsm4(bhf[jf], ab + OFF_BH + off);
                if (TERMS >= 2) ldsm4(blf[jf], ab + OFF_BL + off);
            }
            #pragma unroll
            for (int i = 0; i < 2; ++i)
                #pragma unroll
                for (int j = 0; j < JN; ++j) {
                    const uint32_t* bh2 = &bhf[j >> 1][(j & 1) * 2];
                    mma(acc[i][j], ahf[i], bh2);
                    if (TERMS >= 2) mma(acc[i][j], ahf[i], &blf[j >> 1][(j & 1) * 2]);
                    if (TERMS == 3) mma(acc[i][j], alf[i], bh2);
                }
        }
    }

    int r0l = lane >> 2, cpair = (lane & 3) * 2;
    #pragma unroll
    for (int i = 0; i < 2; ++i)
        #pragma unroll
        for (int j = 0; j < JN; ++j) {
            int colg = bx * TN + wn + j * 8 + cpair;
            #pragma unroll
            for (int hh2 = 0; hh2 < 2; ++hh2) {
                size_t rowg = rowbase + wm + i * 16 + r0l + hh2 * 8;
                float v0 = acc[i][j][hh2 * 2], v1 = acc[i][j][hh2 * 2 + 1];
                if (MODE == 0) {
                    *(float2*)&Cf[rowg * (size_t)ldn + colg] = make_float2(v0, v1);
                } else if (MODE == 3) {          // Q: scale -> hi only [b,h,i,d]
                    int b = (int)(rowg >> 11), ii = (int)(rowg & 2047);
                    int hd = colg >> 6, d = colg & 63;
                    size_t o = (((size_t)b * HEADS + hd) * NQ + ii) * DHEAD + d;
                    *(half2*)&g_Qh[o] = __floats2half2_rn(v0 * 0.125f, v1 * 0.125f);
                } else if (MODE == 4) {          // KV: K[b,j,d] hi, Vt[b,d,j] hi
                    __half h0 = __float2half_rn(v0), h1 = __float2half_rn(v1);
                    int b = (int)(rowg >> 10), jj = (int)(rowg & 1023);
                    if (colg < 64) {
                        *(half2*)&g_Kh[((size_t)b * NCTX + jj) * DHEAD + colg] =
                            __halves2half2(h0, h1);
                    } else {
                        int d0 = colg - 64;
                        g_Vth[((size_t)b * DHEAD + d0) * NCTX + jj] = h0;
                        g_Vth[((size_t)b * DHEAD + d0 + 1) * NCTX + jj] = h1;
                    }
                } else if (MODE == 6) {          // FF1 interleaved -> silu -> cat
                    int m = colg >> 1;           // v0 = h, v1 = gate
                    float a = (v1 / (1.f + __expf(-v1))) * v0;
                    g_cat[rowg * (size_t)KCAT + DIMM + m] = __float2half_rn(a);
                }
            }
        }
}

// ------------------------- fused flash attention (1-term) ------------------
// Q hi [b,h,i,d]; K hi [b,j,d]; Vt hi [b,d,j]. Writes att into cat cols 0-1023.
__global__ void __launch_bounds__(256, 2) flash_attn(
    const __half* __restrict__ Qh, const __half* __restrict__ Kh,
    const __half* __restrict__ Vt)
{
    extern __shared__ char smem[];
    uint32_t t0 = smem_u32(smem);
    const uint32_t QHO = 0, ST0 = 16384, STSZ = 16384;
    int tid = threadIdx.x, lane = tid & 31, wid = tid >> 5;
    int bh = blockIdx.y, b = bh >> 4, h = bh & 15;
    int i0 = blockIdx.x * 128;
    const __half* Qhp = Qh + (((size_t)b * HEADS + h) * NQ + i0) * DHEAD;
    const __half* Khp = Kh + (size_t)b * NCTX * DHEAD;
    const __half* Vtp = Vt + (size_t)b * DHEAD * NCTX;

    for (int u = tid; u < 128 * 8; u += 256) {
        int r = u >> 3, c = u & 7;
        cp16(t0 + QHO + SWZ(r * 128 + c * 16), Qhp + (size_t)r * DHEAD + c * 8);
    }
    auto load_kv = [&](int t, int s) {
        uint32_t st = t0 + ST0 + s * STSZ;
        int j0 = t * 64;
        for (int u = tid; u < 64 * 8; u += 256) {
            int r = u >> 3, c = u & 7;
            uint32_t d = SWZ(r * 128 + c * 16);
            cp16(st + d,        Khp + (size_t)(j0 + r) * DHEAD + c * 8);
            cp16(st + 8192 + d, Vtp + (size_t)r * NCTX + j0 + c * 8);
        }
    };
    load_kv(0, 0);
    CP_COMMIT();

    float acc_o[8][4] = {};
    float mrow0 = -1e30f, mrow1 = -1e30f, lrow0 = 0.f, lrow1 = 0.f;
    int wm = wid * 16;
    int arow = lane & 15, aksel = (lane >> 4) * 16;
    int brow = (lane & 7) + ((lane >> 4) & 1) * 8, bksel = ((lane >> 3) & 1) * 16;

    for (int t = 0; t < 16; ++t) {
        CP_WAIT0();
        __syncthreads();
        if (t + 1 < 16) load_kv(t + 1, (t + 1) & 1);
        CP_COMMIT();
        uint32_t st = t0 + ST0 + (t & 1) * STSZ;

        // S = Qh Kh^T (1-term)
        float s[8][4] = {};
        #pragma unroll
        for (int kk = 0; kk < 4; ++kk) {
            uint32_t ahf[4];
            ldsm4(ahf, t0 + QHO + SWZ((wm + arow) * 128 + kk * 32 + aksel));
            #pragma unroll
            for (int jf = 0; jf < 4; ++jf) {
                uint32_t bhf[4];
                ldsm4(bhf, st + SWZ((jf * 16 + brow) * 128 + kk * 32 + bksel));
                #pragma unroll
                for (int hf = 0; hf < 2; ++hf)
                    mma(s[jf * 2 + hf], ahf, &bhf[hf * 2]);
            }
        }

        float mx0 = mrow0, mx1 = mrow1;
        #pragma unroll
        for (int nf = 0; nf < 8; ++nf) {
            mx0 = fmaxf(mx0, fmaxf(s[nf][0], s[nf][1]));
            mx1 = fmaxf(mx1, fmaxf(s[nf][2], s[nf][3]));
        }
        mx0 = fmaxf(mx0, __shfl_xor_sync(~0u, mx0, 1));
        mx0 = fmaxf(mx0, __shfl_xor_sync(~0u, mx0, 2));
        mx1 = fmaxf(mx1, __shfl_xor_sync(~0u, mx1, 1));
        mx1 = fmaxf(mx1, __shfl_xor_sync(~0u, mx1, 2));
        float corr0 = __expf(mrow0 - mx0), corr1 = __expf(mrow1 - mx1);
        mrow0 = mx0; mrow1 = mx1;
        float sum0 = 0.f, sum1 = 0.f;
        #pragma unroll
        for (int nf = 0; nf < 8; ++nf) {
            s[nf][0] = __expf(s[nf][0] - mx0); s[nf][1] = __expf(s[nf][1] - mx0);
            s[nf][2] = __expf(s[nf][2] - mx1); s[nf][3] = __expf(s[nf][3] - mx1);
            sum0 += s[nf][0] + s[nf][1]; sum1 += s[nf][2] + s[nf][3];
        }
        sum0 += __shfl_xor_sync(~0u, sum0, 1); sum0 += __shfl_xor_sync(~0u, sum0, 2);
        sum1 += __shfl_xor_sync(~0u, sum1, 1); sum1 += __shfl_xor_sync(~0u, sum1, 2);
        lrow0 = lrow0 * corr0 + sum0;
        lrow1 = lrow1 * corr1 + sum1;
        #pragma unroll
        for (int nf = 0; nf < 8; ++nf) {
            acc_o[nf][0] *= corr0; acc_o[nf][1] *= corr0;
            acc_o[nf][2] *= corr1; acc_o[nf][3] *= corr1;
        }

        // P fragments (hi only)
        uint32_t aph[4][4];
        #pragma unroll
        for (int kf = 0; kf < 4; ++kf)
            #pragma unroll
            for (int q = 0; q < 4; ++q) {
                int nf = kf * 2 + (q >> 1), base = (q & 1) * 2;
                half2 hp = __floats2half2_rn(s[nf][base], s[nf][base + 1]);
                aph[kf][q] = *(uint32_t*)&hp;
            }

        // O += P V (1-term)
        #pragma unroll
        for (int kf = 0; kf < 4; ++kf)
            #pragma unroll
            for (int df = 0; df < 4; ++df) {
                uint32_t bv[4];
                ldsm4(bv, st + 8192 + SWZ((df * 16 + brow) * 128 + kf * 32 + bksel));
                #pragma unroll
                for (int hf = 0; hf < 2; ++hf)
                    mma(acc_o[df * 2 + hf], aph[kf], &bv[hf * 2]);
            }
    }

    float inv0 = 1.f / lrow0, inv1 = 1.f / lrow1;
    int r0 = wm + (lane >> 2), cpair = (lane & 3) * 2;
    #pragma unroll
    for (int nf = 0; nf < 8; ++nf) {
        int d = nf * 8 + cpair;
        size_t o0 = ((size_t)b * NQ + (i0 + r0)) * KCAT + h * DHEAD + d;
        size_t o1 = ((size_t)b * NQ + (i0 + r0 + 8)) * KCAT + h * DHEAD + d;
        *(half2*)&g_cat[o0] = __floats2half2_rn(acc_o[nf][0] * inv0, acc_o[nf][1] * inv0);
        *(half2*)&g_cat[o1] = __floats2half2_rn(acc_o[nf][2] * inv1, acc_o[nf][3] * inv1);
    }
}

// ------------------------- LayerNorm -> fp16 (optional lo) ----------------
__global__ __launch_bounds__(256) void ln_split(
    const float* __restrict__ x, const float* __restrict__ g,
    const float* __restrict__ b, __half* __restrict__ yh, __half* __restrict__ yl)
{
    int row = blockIdx.x;
    const float* xr = x + (size_t)row * DIMM;
    float s = 0.f, s2 = 0.f;
    for (int c = threadIdx.x; c < DIMM; c += 256) { float v = xr[c]; s += v; s2 += v * v; }
    __shared__ float red[64];
    #pragma unroll
    for (int o = 16; o; o >>= 1) {
        s += __shfl_xor_sync(~0u, s, o); s2 += __shfl_xor_sync(~0u, s2, o);
    }
    int w = threadIdx.x >> 5, l = threadIdx.x & 31;
    if (l == 0) { red[w] = s; red[32 + w] = s2; }
    __syncthreads();
    if (w == 0) {
        s = (l < 8) ? red[l] : 0.f; s2 = (l < 8) ? red[32 + l] : 0.f;
        #pragma unroll
        for (int o = 4; o; o >>= 1) {
            s += __shfl_xor_sync(~0u, s, o); s2 += __shfl_xor_sync(~0u, s2, o);
        }
        if (l == 0) { red[0] = s; red[1] = s2; }
    }
    __syncthreads();
    float mu = red[0] / DIMM, var = red[1] / DIMM - mu * mu, inv = rsqrtf(var + 1e-5f);
    for (int c = threadIdx.x; c < DIMM; c += 256) {
        float v = (xr[c] - mu) * inv * g[c] + b[c];
        __half h = __float2half_rn(v);
        yh[(size_t)row * DIMM + c] = h;
        if (yl) yl[(size_t)row * DIMM + c] = __float2half_rn(v - __half2float(h));
    }
}

// ------------------------- W[K,N] -> transposed [N,K] (strided dst) -------
__global__ __launch_bounds__(256) void wsplit(
    const float* __restrict__ W, __half* __restrict__ Bh, __half* __restrict__ Bl,
    int K, int N, int ilv, int dstK, int koff)
{
    __shared__ float t[32][33];
    int n0 = blockIdx.x * 32, k0 = blockIdx.y * 32;
    int tx = threadIdx.x & 31, ty = threadIdx.x >> 5;
    #pragma unroll
    for (int r = 0; r < 32; r += 8)
        t[ty + r][tx] = W[(size_t)(k0 + ty + r) * N + n0 + tx];
    __syncthreads();
    #pragma unroll
    for (int r = 0; r < 32; r += 8) {
        float v = t[tx][ty + r];
        __half h = __float2half_rn(v);
        int n = n0 + ty + r;
        int nd = ilv ? ((n < (N >> 1)) ? (n * 2) : ((n - (N >> 1)) * 2 + 1)) : n;
        size_t o = (size_t)nd * dstK + koff + k0 + tx;
        Bh[o] = h;
        if (Bl) Bl[o] = __float2half_rn(v - __half2float(h));
    }
}

// ------------------------- launch -----------------------------------------
static void* sym(const void* s) { void* p = 0; cudaGetSymbolAddress(&p, s); return p; }

extern "C" void kernel_launch(void* const* d_in, const int* in_sizes, int n_in,
                              void* d_out, int out_size)
{
    const float* x    = (const float*)d_in[0];
    const float* ctx  = (const float*)d_in[1];
    const float* lng  = (const float*)d_in[2];
    const float* lnb  = (const float*)d_in[3];
    const float* clng = (const float*)d_in[4];
    const float* clnb = (const float*)d_in[5];
    const float* Wq   = (const float*)d_in[6];
    const float* Wkv  = (const float*)d_in[7];
    const float* Wo   = (const float*)d_in[8];
    const float* Wff1 = (const float*)d_in[9];
    const float* Wff2 = (const float*)d_in[10];
    float* out = (float*)d_out;

    __half *xnh = (__half*)sym(g_xnh);
    __half *cnh = (__half*)sym(g_cnh), *cnl = (__half*)sym(g_cnl);
    __half *Qh = (__half*)sym(g_Qh);
    __half *Kh = (__half*)sym(g_Kh);
    __half *Vt = (__half*)sym(g_Vth);
    __half *cat = (__half*)sym(g_cat);
    __half *Wqh = (__half*)sym(g_Wqh);
    __half *Wkh = (__half*)sym(g_Wkh), *Wkl = (__half*)sym(g_Wkl);
    __half *W1h = (__half*)sym(g_W1h);
    __half *Wcat = (__half*)sym(g_Wcat);

    const int SMEM3 = 4 * 49152;   // 192 KB (3-term, TN=64)
    const int SMEM1 = 3 * 32768;   //  96 KB (1-term, TN=128)
    const int FSMEM = 16384 + 2 * 16384;   // 48 KB flash
    cudaFuncSetAttribute(gemm_hs<0,1,128>, cudaFuncAttributeMaxDynamicSharedMemorySize, SMEM1);
    cudaFuncSetAttribute(gemm_hs<3,1,128>, cudaFuncAttributeMaxDynamicSharedMemorySize, SMEM1);
    cudaFuncSetAttribute(gemm_hs<6,1,128>, cudaFuncAttributeMaxDynamicSharedMemorySize, SMEM1);
    cudaFuncSetAttribute(gemm_hs<4,3,64>,  cudaFuncAttributeMaxDynamicSharedMemorySize, SMEM3);
    cudaFuncSetAttribute(flash_attn, cudaFuncAttributeMaxDynamicSharedMemorySize, FSMEM);

    // weight prep
    wsplit<<<dim3(DIMM/32, DIMM/32), 256>>>(Wq,   Wqh, 0,   DIMM, DIMM, 0, DIMM, 0);
    wsplit<<<dim3(128/32,  DIMM/32), 256>>>(Wkv,  Wkh, Wkl, DIMM, 128,  0, DIMM, 0);
    wsplit<<<dim3(8192/32, DIMM/32), 256>>>(Wff1, W1h, 0,   DIMM, 8192, 1, DIMM, 0);
    // combined B: [Wo | Wff2] rows of 5120
    wsplit<<<dim3(DIMM/32, DIMM/32), 256>>>(Wo,   Wcat, 0,  DIMM, DIMM, 0, KCAT, 0);
    wsplit<<<dim3(DIMM/32, FFI/32),  256>>>(Wff2, Wcat, 0,  FFI,  DIMM, 0, KCAT, DIMM);

    // layernorms (x: hi only; ctx: split for 3-term KV)
    ln_split<<<BATCH*NQ,   256>>>(x,   lng,  lnb,  xnh, 0);
    ln_split<<<BATCH*NCTX, 256>>>(ctx, clng, clnb, cnh, cnl);

    // Q = xn@Wq (scale fused) -> hi [b,h,i,d]      (1-term, TN=128)
    gemm_hs<3,1,128><<<dim3(8, 64), 256, SMEM1>>>(xnh, xnh, Wqh, Wqh, 0, DIMM, DIMM, 0, 0);
    // KV = cn@Wkv -> K hi, Vt hi                   (3-term, TN=64)
    gemm_hs<4,3,64><<<dim3(2, 32), 256, SMEM3>>>(cnh, cnl, Wkh, Wkl, 0, DIMM, 128, 0, 0);
    // fused attention -> cat cols 0..1023
    flash_attn<<<dim3(NQ/128, BATCH*HEADS), 256, FSMEM>>>(Qh, Kh, Vt);
    // FF1 (interleaved) -> silu -> cat cols 1024..5119   (1-term, TN=128)
    gemm_hs<6,1,128><<<dim3(64, 64), 256, SMEM1>>>(xnh, xnh, W1h, W1h, 0, DIMM, 8192, 0, 0);
    // out = cat @ Wcat^T  (K=5120, single fused output GEMM)
    gemm_hs<0,1,128><<<dim3(8, 64), 256, SMEM1>>>(cat, cat, Wcat, Wcat, out, KCAT, DIMM, 0, 0);
}

// round 11
// speedup vs baseline: 1.9320x; 1.0529x over previous
#include <cuda_runtime.h>
#include <cuda_fp16.h>
#include <math.h>
#include <stdint.h>

#define BATCH 4
#define NQ    2048
#define NCTX  1024
#define DIMM  1024
#define HEADS 16
#define DHEAD 64
#define FFI   4096
#define KCAT  5120   // 1024 (att) + 4096 (act)
#define NQF   9216   // 8192 (ff1 interleaved) + 1024 (Wq)

// ------------------------- static scratch ---------------------------------
__device__ __align__(1024) __half g_xnh [(size_t)BATCH*NQ*DIMM];
__device__ __align__(1024) __half g_cnh [(size_t)BATCH*NCTX*DIMM];
__device__ __align__(1024) __half g_Qh  [(size_t)BATCH*HEADS*NQ*DHEAD];
__device__ __align__(1024) __half g_Kh  [(size_t)BATCH*NCTX*DHEAD];
__device__ __align__(1024) __half g_Vth [(size_t)BATCH*DHEAD*NCTX];
__device__ __align__(1024) __half g_cat [(size_t)BATCH*NQ*KCAT];   // [att | act]
__device__ __align__(1024) __half g_Wkh [(size_t)2*DHEAD*DIMM];
__device__ __align__(1024) __half g_W1q [(size_t)NQF*DIMM];        // [W1 ilv | Wq]
__device__ __align__(1024) __half g_Wcat[(size_t)DIMM*KCAT];       // [Wo | Wff2]

// ------------------------- helpers ----------------------------------------
__device__ __forceinline__ uint32_t smem_u32(const void* p) {
    uint32_t a;
    asm("{ .reg .u64 t; cvta.to.shared.u64 t, %1; cvt.u32.u64 %0, t; }" : "=r"(a) : "l"(p));
    return a;
}
#define SWZ(x) ((x) ^ (((x) >> 3) & 0x70))
__device__ __forceinline__ void cp16(uint32_t dst, const void* src) {
    asm volatile("cp.async.cg.shared.global [%0], [%1], 16;\n" :: "r"(dst), "l"(src));
}
#define CP_COMMIT() asm volatile("cp.async.commit_group;\n" ::: "memory")
#define CP_WAIT0()  asm volatile("cp.async.wait_group 0;\n"  ::: "memory")
#define CP_WAIT1()  asm volatile("cp.async.wait_group 1;\n"  ::: "memory")
__device__ __forceinline__ void ldsm4(uint32_t* r, uint32_t a) {
    asm volatile("ldmatrix.sync.aligned.m8n8.x4.shared.b16 {%0,%1,%2,%3}, [%4];"
                 : "=r"(r[0]), "=r"(r[1]), "=r"(r[2]), "=r"(r[3]) : "r"(a));
}
__device__ __forceinline__ void mma(float* c, const uint32_t* a, const uint32_t* b) {
    asm volatile("mma.sync.aligned.m16n8k16.row.col.f32.f16.f16.f32 "
                 "{%0,%1,%2,%3}, {%4,%5,%6,%7}, {%8,%9}, {%0,%1,%2,%3};"
                 : "+f"(c[0]), "+f"(c[1]), "+f"(c[2]), "+f"(c[3])
                 : "r"(a[0]), "r"(a[1]), "r"(a[2]), "r"(a[3]), "r"(b[0]), "r"(b[1]));
}

// ------------------------- GEMM (HMMA fp16, 1-term) ------------------------
// C[M x Ntot] = A[M,K] @ B[N,K]^T ; BM=128, BN=128, BK=64, 8 warps,
// 3-stage 32KB ring, 2 CTA/SM.
// MODE: 0 f32 store, 4 KV epilogue, 7 merged FF1(silu->cat)+Q epilogue
template <int MODE>
__global__ void __launch_bounds__(256, 2) gemm_hs(
    const __half* __restrict__ Ah, const __half* __restrict__ Bh,
    float* __restrict__ Cf, int K, int ldn)
{
    constexpr int OFF_BH = 16384;
    constexpr int STAGE  = 32768;
    constexpr int NS     = 3;
    extern __shared__ char smem[];
    uint32_t t0 = smem_u32(smem);
    int tid = threadIdx.x, lane = tid & 31, wid = tid >> 5;

    // L2-friendly supertile rasterization (groups of 8 output-row blocks)
    int bx = blockIdx.x, by = blockIdx.y;
    if ((gridDim.y & 7) == 0) {
        int lin = by * gridDim.x + bx;
        int seg = gridDim.x * 8;
        int band = lin / seg, rem = lin % seg;
        by = band * 8 + (rem & 7);
        bx = rem >> 3;
    }

    size_t rowbase = (size_t)by * 128;
    const __half* As = Ah + rowbase * K;
    const __half* Bs = Bh + (size_t)bx * 128 * K;
    const int nch = K >> 6;

    auto load_chunk = [&](int c, int s) {
        uint32_t st = t0 + s * STAGE;
        int k0 = c << 6;
        #pragma unroll
        for (int u = tid; u < 1024; u += 256) {
            int r = u >> 3, cc = u & 7;
            cp16(st + SWZ(r * 128 + cc * 16), As + (size_t)r * K + k0 + cc * 8);
        }
        #pragma unroll
        for (int u = tid; u < 1024; u += 256) {
            int r = u >> 3, cc = u & 7;
            cp16(st + OFF_BH + SWZ(r * 128 + cc * 16), Bs + (size_t)r * K + k0 + cc * 8);
        }
    };

    for (int p = 0; p < NS - 1; ++p) { if (p < nch) load_chunk(p, p); CP_COMMIT(); }

    float acc[2][8][4] = {};
    int wm = (wid & 3) * 32, wn = (wid >> 2) * 64;
    int arow = lane & 15, aksel = (lane >> 4) * 16;
    int brow = (lane & 7) + ((lane >> 4) & 1) * 8, bksel = ((lane >> 3) & 1) * 16;

    for (int c = 0; c < nch; ++c) {
        CP_WAIT1();
        __syncthreads();
        if (c + NS - 1 < nch) load_chunk(c + NS - 1, (c + NS - 1) % NS);
        CP_COMMIT();
        uint32_t ab = t0 + (c % NS) * STAGE;
        #pragma unroll
        for (int kk = 0; kk < 4; ++kk) {
            uint32_t ahf[2][4], bhf[4][4];
            #pragma unroll
            for (int i = 0; i < 2; ++i)
                ldsm4(ahf[i], ab + SWZ((wm + i * 16 + arow) * 128 + kk * 32 + aksel));
            #pragma unroll
            for (int jf = 0; jf < 4; ++jf)
                ldsm4(bhf[jf], ab + OFF_BH +
                      SWZ((wn + jf * 16 + brow) * 128 + kk * 32 + bksel));
            #pragma unroll
            for (int i = 0; i < 2; ++i)
                #pragma unroll
                for (int j = 0; j < 8; ++j)
                    mma(acc[i][j], ahf[i], &bhf[j >> 1][(j & 1) * 2]);
        }
    }

    int r0l = lane >> 2, cpair = (lane & 3) * 2;
    #pragma unroll
    for (int i = 0; i < 2; ++i)
        #pragma unroll
        for (int j = 0; j < 8; ++j) {
            int colg = bx * 128 + wn + j * 8 + cpair;
            #pragma unroll
            for (int hh2 = 0; hh2 < 2; ++hh2) {
                size_t rowg = rowbase + wm + i * 16 + r0l + hh2 * 8;
                float v0 = acc[i][j][hh2 * 2], v1 = acc[i][j][hh2 * 2 + 1];
                if (MODE == 0) {
                    *(float2*)&Cf[rowg * (size_t)ldn + colg] = make_float2(v0, v1);
                } else if (MODE == 4) {          // KV: K[b,j,d] hi, Vt[b,d,j] hi
                    __half h0 = __float2half_rn(v0), h1 = __float2half_rn(v1);
                    int b = (int)(rowg >> 10), jj = (int)(rowg & 1023);
                    if (colg < 64) {
                        *(half2*)&g_Kh[((size_t)b * NCTX + jj) * DHEAD + colg] =
                            __halves2half2(h0, h1);
                    } else {
                        int d0 = colg - 64;
                        g_Vth[((size_t)b * DHEAD + d0) * NCTX + jj] = h0;
                        g_Vth[((size_t)b * DHEAD + d0 + 1) * NCTX + jj] = h1;
                    }
                } else if (MODE == 7) {          // merged FF1-silu / Q epilogue
                    if (colg < 8192) {           // v0 = h, v1 = gate
                        float a = (v1 / (1.f + __expf(-v1))) * v0;
                        g_cat[rowg * (size_t)KCAT + DIMM + (colg >> 1)] =
                            __float2half_rn(a);
                    } else {
                        int qc = colg - 8192;
                        int b = (int)(rowg >> 11), ii = (int)(rowg & 2047);
                        int hd = qc >> 6, d = qc & 63;
                        size_t o = (((size_t)b * HEADS + hd) * NQ + ii) * DHEAD + d;
                        *(half2*)&g_Qh[o] =
                            __floats2half2_rn(v0 * 0.125f, v1 * 0.125f);
                    }
                }
            }
        }
}

// ------------------------- fused flash attention (1-term) ------------------
__global__ void __launch_bounds__(256, 2) flash_attn(
    const __half* __restrict__ Qh, const __half* __restrict__ Kh,
    const __half* __restrict__ Vt)
{
    extern __shared__ char smem[];
    uint32_t t0 = smem_u32(smem);
    const uint32_t QHO = 0, ST0 = 16384, STSZ = 16384;
    int tid = threadIdx.x, lane = tid & 31, wid = tid >> 5;
    int bh = blockIdx.y, b = bh >> 4, h = bh & 15;
    int i0 = blockIdx.x * 128;
    const __half* Qhp = Qh + (((size_t)b * HEADS + h) * NQ + i0) * DHEAD;
    const __half* Khp = Kh + (size_t)b * NCTX * DHEAD;
    const __half* Vtp = Vt + (size_t)b * DHEAD * NCTX;

    for (int u = tid; u < 128 * 8; u += 256) {
        int r = u >> 3, c = u & 7;
        cp16(t0 + QHO + SWZ(r * 128 + c * 16), Qhp + (size_t)r * DHEAD + c * 8);
    }
    auto load_kv = [&](int t, int s) {
        uint32_t st = t0 + ST0 + s * STSZ;
        int j0 = t * 64;
        for (int u = tid; u < 64 * 8; u += 256) {
            int r = u >> 3, c = u & 7;
            uint32_t d = SWZ(r * 128 + c * 16);
            cp16(st + d,        Khp + (size_t)(j0 + r) * DHEAD + c * 8);
            cp16(st + 8192 + d, Vtp + (size_t)r * NCTX + j0 + c * 8);
        }
    };
    load_kv(0, 0);
    CP_COMMIT();

    float acc_o[8][4] = {};
    float mrow0 = -1e30f, mrow1 = -1e30f, lrow0 = 0.f, lrow1 = 0.f;
    int wm = wid * 16;
    int arow = lane & 15, aksel = (lane >> 4) * 16;
    int brow = (lane & 7) + ((lane >> 4) & 1) * 8, bksel = ((lane >> 3) & 1) * 16;

    for (int t = 0; t < 16; ++t) {
        CP_WAIT0();
        __syncthreads();
        if (t + 1 < 16) load_kv(t + 1, (t + 1) & 1);
        CP_COMMIT();
        uint32_t st = t0 + ST0 + (t & 1) * STSZ;

        float s[8][4] = {};
        #pragma unroll
        for (int kk = 0; kk < 4; ++kk) {
            uint32_t ahf[4];
            ldsm4(ahf, t0 + QHO + SWZ((wm + arow) * 128 + kk * 32 + aksel));
            #pragma unroll
            for (int jf = 0; jf < 4; ++jf) {
                uint32_t bhf[4];
                ldsm4(bhf, st + SWZ((jf * 16 + brow) * 128 + kk * 32 + bksel));
                #pragma unroll
                for (int hf = 0; hf < 2; ++hf)
                    mma(s[jf * 2 + hf], ahf, &bhf[hf * 2]);
            }
        }

        float mx0 = mrow0, mx1 = mrow1;
        #pragma unroll
        for (int nf = 0; nf < 8; ++nf) {
            mx0 = fmaxf(mx0, fmaxf(s[nf][0], s[nf][1]));
            mx1 = fmaxf(mx1, fmaxf(s[nf][2], s[nf][3]));
        }
        mx0 = fmaxf(mx0, __shfl_xor_sync(~0u, mx0, 1));
        mx0 = fmaxf(mx0, __shfl_xor_sync(~0u, mx0, 2));
        mx1 = fmaxf(mx1, __shfl_xor_sync(~0u, mx1, 1));
        mx1 = fmaxf(mx1, __shfl_xor_sync(~0u, mx1, 2));
        float corr0 = __expf(mrow0 - mx0), corr1 = __expf(mrow1 - mx1);
        mrow0 = mx0; mrow1 = mx1;
        float sum0 = 0.f, sum1 = 0.f;
        #pragma unroll
        for (int nf = 0; nf < 8; ++nf) {
            s[nf][0] = __expf(s[nf][0] - mx0); s[nf][1] = __expf(s[nf][1] - mx0);
            s[nf][2] = __expf(s[nf][2] - mx1); s[nf][3] = __expf(s[nf][3] - mx1);
            sum0 += s[nf][0] + s[nf][1]; sum1 += s[nf][2] + s[nf][3];
        }
        sum0 += __shfl_xor_sync(~0u, sum0, 1); sum0 += __shfl_xor_sync(~0u, sum0, 2);
        sum1 += __shfl_xor_sync(~0u, sum1, 1); sum1 += __shfl_xor_sync(~0u, sum1, 2);
        lrow0 = lrow0 * corr0 + sum0;
        lrow1 = lrow1 * corr1 + sum1;
        #pragma unroll
        for (int nf = 0; nf < 8; ++nf) {
            acc_o[nf][0] *= corr0; acc_o[nf][1] *= corr0;
            acc_o[nf][2] *= corr1; acc_o[nf][3] *= corr1;
        }

        uint32_t aph[4][4];
        #pragma unroll
        for (int kf = 0; kf < 4; ++kf)
            #pragma unroll
            for (int q = 0; q < 4; ++q) {
                int nf = kf * 2 + (q >> 1), base = (q & 1) * 2;
                half2 hp = __floats2half2_rn(s[nf][base], s[nf][base + 1]);
                aph[kf][q] = *(uint32_t*)&hp;
            }

        #pragma unroll
        for (int kf = 0; kf < 4; ++kf)
            #pragma unroll
            for (int df = 0; df < 4; ++df) {
                uint32_t bv[4];
                ldsm4(bv, st + 8192 + SWZ((df * 16 + brow) * 128 + kf * 32 + bksel));
                #pragma unroll
                for (int hf = 0; hf < 2; ++hf)
                    mma(acc_o[df * 2 + hf], aph[kf], &bv[hf * 2]);
            }
    }

    float inv0 = 1.f / lrow0, inv1 = 1.f / lrow1;
    int r0 = wm + (lane >> 2), cpair = (lane & 3) * 2;
    #pragma unroll
    for (int nf = 0; nf < 8; ++nf) {
        int d = nf * 8 + cpair;
        size_t o0 = ((size_t)b * NQ + (i0 + r0)) * KCAT + h * DHEAD + d;
        size_t o1 = ((size_t)b * NQ + (i0 + r0 + 8)) * KCAT + h * DHEAD + d;
        *(half2*)&g_cat[o0] = __floats2half2_rn(acc_o[nf][0] * inv0, acc_o[nf][1] * inv0);
        *(half2*)&g_cat[o1] = __floats2half2_rn(acc_o[nf][2] * inv1, acc_o[nf][3] * inv1);
    }
}

// ------------------------- fused LayerNorm (x rows then ctx rows) ---------
__global__ __launch_bounds__(256) void ln_all(
    const float* __restrict__ x, const float* __restrict__ ctx,
    const float* __restrict__ lng, const float* __restrict__ lnb,
    const float* __restrict__ clng, const float* __restrict__ clnb)
{
    int row = blockIdx.x;
    const float* xr;
    const float* g;
    const float* b;
    __half* dst;
    if (row < BATCH * NQ) {
        xr = x + (size_t)row * DIMM; g = lng; b = lnb;
        dst = g_xnh + (size_t)row * DIMM;
    } else {
        int r = row - BATCH * NQ;
        xr = ctx + (size_t)r * DIMM; g = clng; b = clnb;
        dst = g_cnh + (size_t)r * DIMM;
    }
    float s = 0.f, s2 = 0.f;
    for (int c = threadIdx.x; c < DIMM; c += 256) { float v = xr[c]; s += v; s2 += v * v; }
    __shared__ float red[64];
    #pragma unroll
    for (int o = 16; o; o >>= 1) {
        s += __shfl_xor_sync(~0u, s, o); s2 += __shfl_xor_sync(~0u, s2, o);
    }
    int w = threadIdx.x >> 5, l = threadIdx.x & 31;
    if (l == 0) { red[w] = s; red[32 + w] = s2; }
    __syncthreads();
    if (w == 0) {
        s = (l < 8) ? red[l] : 0.f; s2 = (l < 8) ? red[32 + l] : 0.f;
        #pragma unroll
        for (int o = 4; o; o >>= 1) {
            s += __shfl_xor_sync(~0u, s, o); s2 += __shfl_xor_sync(~0u, s2, o);
        }
        if (l == 0) { red[0] = s; red[1] = s2; }
    }
    __syncthreads();
    float mu = red[0] / DIMM, var = red[1] / DIMM - mu * mu, inv = rsqrtf(var + 1e-5f);
    for (int c = threadIdx.x; c < DIMM; c += 256)
        dst[c] = __float2half_rn((xr[c] - mu) * inv * g[c] + b[c]);
}

// ------------------------- fused weight transpose/convert ------------------
// jobs (tile counts): Wq->W1q[8192:] 1024 | Wkv->Wkh 128 | Wff1->W1q[:8192] ilv 8192
//                     Wo->Wcat[:,0:1024] 1024 | Wff2->Wcat[:,1024:] 4096
__global__ __launch_bounds__(256) void wsplit_all(
    const float* __restrict__ Wq, const float* __restrict__ Wkv,
    const float* __restrict__ Wo, const float* __restrict__ Wff1,
    const float* __restrict__ Wff2)
{
    int t = blockIdx.x;
    const float* W; __half* Bh; int K, N, ilv, dstK;
    if (t < 1024)       { W = Wq;   Bh = g_W1q + (size_t)8192 * DIMM; K = 1024; N = 1024; ilv = 0; dstK = 1024; }
    else if (t < 1152)  { t -= 1024;  W = Wkv;  Bh = g_Wkh;  K = 1024; N = 128;  ilv = 0; dstK = 1024; }
    else if (t < 9344)  { t -= 1152;  W = Wff1; Bh = g_W1q;  K = 1024; N = 8192; ilv = 1; dstK = 1024; }
    else if (t < 10368) { t -= 9344;  W = Wo;   Bh = g_Wcat; K = 1024; N = 1024; ilv = 0; dstK = 5120; }
    else                { t -= 10368; W = Wff2; Bh = g_Wcat + 1024; K = 4096; N = 1024; ilv = 0; dstK = 5120; }
    int nx = N >> 5;
    int n0 = (t % nx) * 32, k0 = (t / nx) * 32;

    __shared__ float tt[32][33];
    int tx = threadIdx.x & 31, ty = threadIdx.x >> 5;
    #pragma unroll
    for (int r = 0; r < 32; r += 8)
        tt[ty + r][tx] = W[(size_t)(k0 + ty + r) * N + n0 + tx];
    __syncthreads();
    #pragma unroll
    for (int r = 0; r < 32; r += 8) {
        float v = tt[tx][ty + r];
        int n = n0 + ty + r;
        int nd = ilv ? ((n < (N >> 1)) ? (n * 2) : ((n - (N >> 1)) * 2 + 1)) : n;
        Bh[(size_t)nd * dstK + k0 + tx] = __float2half_rn(v);
    }
}

// ------------------------- launch -----------------------------------------
static void* sym(const void* s) { void* p = 0; cudaGetSymbolAddress(&p, s); return p; }

extern "C" void kernel_launch(void* const* d_in, const int* in_sizes, int n_in,
                              void* d_out, int out_size)
{
    const float* x    = (const float*)d_in[0];
    const float* ctx  = (const float*)d_in[1];
    const float* lng  = (const float*)d_in[2];
    const float* lnb  = (const float*)d_in[3];
    const float* clng = (const float*)d_in[4];
    const float* clnb = (const float*)d_in[5];
    const float* Wq   = (const float*)d_in[6];
    const float* Wkv  = (const float*)d_in[7];
    const float* Wo   = (const float*)d_in[8];
    const float* Wff1 = (const float*)d_in[9];
    const float* Wff2 = (const float*)d_in[10];
    float* out = (float*)d_out;

    __half *xnh = (__half*)sym(g_xnh), *cnh = (__half*)sym(g_cnh);
    __half *Qh = (__half*)sym(g_Qh), *Kh = (__half*)sym(g_Kh), *Vt = (__half*)sym(g_Vth);
    __half *cat = (__half*)sym(g_cat);
    __half *Wkh = (__half*)sym(g_Wkh);
    __half *W1q = (__half*)sym(g_W1q);
    __half *Wcat = (__half*)sym(g_Wcat);

    const int SMEM1 = 3 * 32768;           // 96 KB GEMM
    const int FSMEM = 16384 + 2 * 16384;   // 48 KB flash
    cudaFuncSetAttribute(gemm_hs<0>, cudaFuncAttributeMaxDynamicSharedMemorySize, SMEM1);
    cudaFuncSetAttribute(gemm_hs<4>, cudaFuncAttributeMaxDynamicSharedMemorySize, SMEM1);
    cudaFuncSetAttribute(gemm_hs<7>, cudaFuncAttributeMaxDynamicSharedMemorySize, SMEM1);
    cudaFuncSetAttribute(flash_attn, cudaFuncAttributeMaxDynamicSharedMemorySize, FSMEM);

    // 1) all weight prep, one launch (14464 tile-blocks)
    wsplit_all<<<14464, 256>>>(Wq, Wkv, Wo, Wff1, Wff2);
    // 2) both layernorms, one launch
    ln_all<<<BATCH*NQ + BATCH*NCTX, 256>>>(x, ctx, lng, lnb, clng, clnb);
    // 3) KV = cn@Wkv -> K hi, Vt hi (1-term)
    gemm_hs<4><<<dim3(1, 32), 256, SMEM1>>>(cnh, Wkh, 0, DIMM, 128);
    // 4) merged [FF1-silu | Q] GEMM over N=9216
    gemm_hs<7><<<dim3(NQF/128, 64), 256, SMEM1>>>(xnh, W1q, 0, DIMM, NQF);
    // 5) fused attention -> cat cols 0..1023
    flash_attn<<<dim3(NQ/128, BATCH*HEADS), 256, FSMEM>>>(Qh, Kh, Vt);
    // 6) out = cat @ Wcat^T (K=5120)
    gemm_hs<0><<<dim3(8, 64), 256, SMEM1>>>(cat, Wcat, out, KCAT, DIMM);
}